// round 12
// baseline (speedup 1.0000x reference)
#include <cuda_runtime.h>
#include <cuda_bf16.h>
#include <cuda_fp16.h>
#include <math.h>
#include <stdint.h>

#define Nn   50000
#define Ee   800000
#define EN   (Ee + Nn)
#define Hh   128
#define FIN  64
#define NEGS 0.2f
#define LNEPS 1e-5f
#define NB_SCAN 49   // ceil(50000/1024)

#define OFF_WIN 0
#define OFF_WLR 8192                     // 128*64
#define OFF_W1  (8192 + 3 * 256 * 128)   // 106496
#define TOTW    (OFF_W1 + 64 * 128)      // 114688

// ---------------- scratch (static device globals; no allocation) -------------
__device__ float g_h [Nn * Hh];
__device__ float g_xl[Nn * Hh];          // t1 scratch for MLP
__device__ float g_xr[Nn * Hh];
__device__ __align__(16) __half g_xlh[Nn * Hh];   // xl fp16 for the gather
__device__ float g_dv[Nn];               // at . xl[node]
__device__ float g_dr[Nn];               // at . xr[node]
__device__ int   g_deg[Nn];
__device__ int   g_incl[Nn];
__device__ int   g_rowptr[Nn + 1];
__device__ int   g_cursor[Nn + 1];
__device__ int   g_esrc[EN];
__device__ int   g_bsums[64];
__device__ int   g_dbin[64];
__device__ int   g_dcur[64];
__device__ int   g_order[Nn];            // nodes sorted by degree
__device__ __align__(16) __nv_bfloat16 g_bwh[TOTW];
__device__ __align__(16) __nv_bfloat16 g_bwl[TOTW];
__device__ __align__(16) __nv_bfloat16 g_xs_h[Nn * FIN];
__device__ __align__(16) __nv_bfloat16 g_xs_l[Nn * FIN];
__device__ __align__(16) __nv_bfloat16 g_hs_h[Nn * Hh];
__device__ __align__(16) __nv_bfloat16 g_hs_l[Nn * Hh];

// ---------------- weight split/convert (fp32 -> bf16 hi/lo, n-major) ---------
__global__ void wconvert_kernel(const float* __restrict__ Win, const float* __restrict__ Wl,
                                const float* __restrict__ Wr, const float* __restrict__ W1)
{
    int i = blockIdx.x * blockDim.x + threadIdx.x;
    if (i < Nn) g_deg[i] = 1;
    if (i < 64) g_dbin[i] = 0;
    if (i >= TOTW) return;
    float v;
    if (i < OFF_WLR) {                       // Win [64,128] -> n-major [128][64]
        int n = i >> 6, k = i & 63;
        v = Win[k * 128 + n];
    } else if (i < OFF_W1) {                 // Wl||Wr per layer -> [256][128]
        int j = i - OFF_WLR;
        int l = j >> 15, r = j & 32767;
        int n = r >> 7, k = r & 127;
        v = (n < 128) ? Wl[l * 16384 + k * 128 + n]
                      : Wr[l * 16384 + k * 128 + (n - 128)];
    } else {                                 // W1 [128,64] -> n-major [64][128]
        int j = i - OFF_W1;
        int n = j >> 7, k = j & 127;
        v = W1[k * 64 + n];
    }
    __nv_bfloat16 hi = __float2bfloat16(v);
    g_bwh[i] = hi;
    g_bwl[i] = __float2bfloat16(v - __bfloat162float(hi));
}

// x split + edge histogram (fused: grid covers Nn*FIN >= Ee)
__global__ void xconvert_kernel(const float* __restrict__ x, const int* __restrict__ dst) {
    int i = blockIdx.x * blockDim.x + threadIdx.x;
    if (i < Nn * FIN) {
        float v = x[i];
        __nv_bfloat16 hi = __float2bfloat16(v);
        g_xs_h[i] = hi;
        g_xs_l[i] = __float2bfloat16(v - __bfloat162float(hi));
    }
    if (i < Ee) atomicAdd(&g_deg[dst[i]], 1);
}

// ---------------- degree bucket sort -----------------------------------------
__global__ void dsort_hist_kernel() {
    __shared__ int sb[64];
    if (threadIdx.x < 64) sb[threadIdx.x] = 0;
    __syncthreads();
    int i = blockIdx.x * blockDim.x + threadIdx.x;
    if (i < Nn) atomicAdd(&sb[min(g_deg[i] - 1, 63)], 1);
    __syncthreads();
    if (threadIdx.x < 64 && sb[threadIdx.x])
        atomicAdd(&g_dbin[threadIdx.x], sb[threadIdx.x]);
}

__global__ void dsort_scan_kernel() {
    if (threadIdx.x == 0) {
        int run = 0;
        for (int j = 0; j < 64; ++j) { int t = g_dbin[j]; g_dcur[j] = run; run += t; }
    }
}

__global__ void dsort_scatter_kernel() {
    int i = blockIdx.x * blockDim.x + threadIdx.x;
    if (i < Nn) {
        int p = atomicAdd(&g_dcur[min(g_deg[i] - 1, 63)], 1);
        g_order[p] = i;
    }
}

// ---------------- CSR build --------------------------------------------------
__global__ void scan1_kernel() {
    __shared__ int sm[1024];
    int i = blockIdx.x * 1024 + threadIdx.x;
    int v = (i < Nn) ? g_deg[i] : 0;
    sm[threadIdx.x] = v;
    __syncthreads();
    #pragma unroll
    for (int off = 1; off < 1024; off <<= 1) {
        int t = 0;
        if ((int)threadIdx.x >= off) t = sm[threadIdx.x - off];
        __syncthreads();
        sm[threadIdx.x] += t;
        __syncthreads();
    }
    if (i < Nn) g_incl[i] = sm[threadIdx.x];
    if (threadIdx.x == 1023) g_bsums[blockIdx.x] = sm[1023];
}

__global__ void scan3_kernel() {
    __shared__ int base_s;
    if (threadIdx.x == 0) {
        int b = 0;
        for (int j = 0; j < (int)blockIdx.x; ++j) b += g_bsums[j];
        base_s = b;
    }
    __syncthreads();
    int i = blockIdx.x * 1024 + threadIdx.x;
    if (i < Nn) {
        int val = g_incl[i] + base_s;
        g_rowptr[i + 1] = val;
        g_cursor[i + 1] = val;
        if (i == 0) { g_rowptr[0] = 0; g_cursor[0] = 0; }
    }
}

__global__ void scatter_kernel(const int* __restrict__ src, const int* __restrict__ dst) {
    int e = blockIdx.x * blockDim.x + threadIdx.x;
    if (e < EN) {
        int s, d;
        if (e < Ee) { s = src[e]; d = dst[e]; }
        else        { s = d = e - Ee; }
        int p = atomicAdd(&g_cursor[d], 1);
        g_esrc[p] = s;
    }
}

// ---------------- bf16x3 tensor-core GEMM (32x64 warp tiles, cp.async) -------
__device__ __forceinline__ void mma16816(float* c, const unsigned* a, const unsigned* b) {
    asm volatile(
        "mma.sync.aligned.m16n8k16.row.col.f32.bf16.bf16.f32 "
        "{%0,%1,%2,%3},{%4,%5,%6,%7},{%8,%9},{%0,%1,%2,%3};"
        : "+f"(c[0]), "+f"(c[1]), "+f"(c[2]), "+f"(c[3])
        : "r"(a[0]), "r"(a[1]), "r"(a[2]), "r"(a[3]), "r"(b[0]), "r"(b[1]));
}

__device__ __forceinline__ void ldsm4(unsigned* r, const __nv_bfloat16* p) {
    unsigned addr = (unsigned)__cvta_generic_to_shared(p);
    asm volatile("ldmatrix.sync.aligned.m8n8.x4.shared.b16 {%0,%1,%2,%3},[%4];"
                 : "=r"(r[0]), "=r"(r[1]), "=r"(r[2]), "=r"(r[3]) : "r"(addr));
}

__device__ __forceinline__ void cpa16(uint32_t dst, const void* src, uint32_t srcsz) {
    asm volatile("cp.async.ca.shared.global [%0], [%1], 16, %2;"
                 :: "r"(dst), "l"(src), "r"(srcsz) : "memory");
}
#define CPA_COMMIT() asm volatile("cp.async.commit_group;" ::: "memory")

#define ARR_E   (128 * 40)
#define BUF_E   (4 * ARR_E)
#define SMEM_B  (2 * BUF_E * 2)          // bytes = 81920

extern __shared__ __nv_bfloat16 smbf[];

__global__ void __launch_bounds__(256, 2) gemm3_kernel(
    const __nv_bfloat16* __restrict__ Ah, const __nv_bfloat16* __restrict__ Al, int lda,
    const __nv_bfloat16* __restrict__ Bh, const __nv_bfloat16* __restrict__ Bl,
    const float* __restrict__ bias0, const float* __restrict__ bias1,
    float* __restrict__ C0, float* __restrict__ C1, __half* __restrict__ C0h,
    __nv_bfloat16* __restrict__ Sh, __nv_bfloat16* __restrict__ Sl,
    int M, int K, int Nvalid, int nsplit, int ldc, int relu)
{
    const int tid = threadIdx.x;
    const int lane = tid & 31;
    const int wid = tid >> 5;
    const int warp_m = wid >> 1;
    const int warp_n = wid & 1;
    const int mrow = lane & 7;
    const int mat  = lane >> 3;

    const int row0 = blockIdx.x * 128;
    const int col0 = blockIdx.y * 128;

    float acc[2][8][4];
    #pragma unroll
    for (int a = 0; a < 2; ++a)
        #pragma unroll
        for (int b = 0; b < 8; ++b)
            #pragma unroll
            for (int c = 0; c < 4; ++c) acc[a][b][c] = 0.f;

    const int r  = tid >> 1;
    const int hf = tid & 1;
    const uint32_t smaddr = (uint32_t)__cvta_generic_to_shared(smbf);
    const uint32_t arow_sz = ((row0 + r) < M) ? 16u : 0u;
    const uint32_t brow_sz = ((col0 + r) < Nvalid) ? 16u : 0u;
    const int nk = K >> 5;

    #define STAGE(ck, buf) do {                                                      \
        int kk_ = (ck) * 32;                                                         \
        uint32_t base_ = smaddr + (uint32_t)((buf) * BUF_E) * 2u;                    \
        uint32_t doff_ = (uint32_t)(r * 40 + hf * 16) * 2u;                          \
        const __nv_bfloat16* pah_ = Ah + (size_t)(row0 + r) * lda + kk_ + hf * 16;   \
        const __nv_bfloat16* pal_ = Al + (size_t)(row0 + r) * lda + kk_ + hf * 16;   \
        cpa16(base_ + doff_,                    pah_,     arow_sz);                  \
        cpa16(base_ + doff_ + 16,               pah_ + 8, arow_sz);                  \
        cpa16(base_ + ARR_E * 2 + doff_,        pal_,     arow_sz);                  \
        cpa16(base_ + ARR_E * 2 + doff_ + 16,   pal_ + 8, arow_sz);                  \
        const __nv_bfloat16* pbh_ = Bh + (size_t)(col0 + r) * K + kk_ + hf * 16;     \
        const __nv_bfloat16* pbl_ = Bl + (size_t)(col0 + r) * K + kk_ + hf * 16;     \
        cpa16(base_ + ARR_E * 4 + doff_,        pbh_,     brow_sz);                  \
        cpa16(base_ + ARR_E * 4 + doff_ + 16,   pbh_ + 8, brow_sz);                  \
        cpa16(base_ + ARR_E * 6 + doff_,        pbl_,     brow_sz);                  \
        cpa16(base_ + ARR_E * 6 + doff_ + 16,   pbl_ + 8, brow_sz);                  \
        CPA_COMMIT();                                                                \
    } while (0)

    STAGE(0, 0);

    for (int ci = 0; ci < nk; ++ci) {
        if (ci + 1 < nk) {
            STAGE(ci + 1, (ci + 1) & 1);
            asm volatile("cp.async.wait_group 1;" ::: "memory");
        } else {
            asm volatile("cp.async.wait_group 0;" ::: "memory");
        }
        __syncthreads();

        const __nv_bfloat16* sAh = smbf + (ci & 1) * BUF_E;
        const __nv_bfloat16* sAl = sAh + ARR_E;
        const __nv_bfloat16* sBh = sAh + 2 * ARR_E;
        const __nv_bfloat16* sBl = sAh + 3 * ARR_E;

        #pragma unroll
        for (int ks = 0; ks < 2; ++ks) {
            const int ck = ks * 16;
            unsigned ah[2][4], al[2][4];
            #pragma unroll
            for (int mt = 0; mt < 2; ++mt) {
                int ar  = warp_m * 32 + mt * 16 + ((mat & 1) << 3) + mrow;
                int acl = ck + ((mat >> 1) << 3);
                ldsm4(ah[mt], sAh + ar * 40 + acl);
                ldsm4(al[mt], sAl + ar * 40 + acl);
            }
            #pragma unroll
            for (int p = 0; p < 4; ++p) {
                unsigned bh4[4], bl4[4];
                int bn  = warp_n * 64 + p * 16 + ((mat >> 1) << 3) + mrow;
                int bcl = ck + ((mat & 1) << 3);
                ldsm4(bh4, sBh + bn * 40 + bcl);
                ldsm4(bl4, sBl + bn * 40 + bcl);
                #pragma unroll
                for (int half = 0; half < 2; ++half) {
                    int nt = p * 2 + half;
                    #pragma unroll
                    for (int mt = 0; mt < 2; ++mt) {
                        mma16816(acc[mt][nt], ah[mt], &bh4[half * 2]);
                        mma16816(acc[mt][nt], al[mt], &bh4[half * 2]);
                        mma16816(acc[mt][nt], ah[mt], &bl4[half * 2]);
                    }
                }
            }
        }
        __syncthreads();
    }

    // ---- epilogue ----
    const float* bp;
    int colbase;
    int useC1 = (col0 >= nsplit);
    if (useC1) { bp = bias1; colbase = col0 - nsplit; }
    else       { bp = bias0; colbase = col0; }

    const int g = lane >> 2, qt = lane & 3;
    #pragma unroll
    for (int mt = 0; mt < 2; ++mt) {
        #pragma unroll
        for (int nt = 0; nt < 8; ++nt) {
            int gcol = col0 + warp_n * 64 + nt * 8 + 2 * qt;
            if (gcol < Nvalid) {
                int oc = colbase + warp_n * 64 + nt * 8 + 2 * qt;
                float b0 = bp[oc], b1 = bp[oc + 1];
                int ra = row0 + warp_m * 32 + mt * 16 + g;
                float v0 = acc[mt][nt][0] + b0, v1 = acc[mt][nt][1] + b1;
                float v2 = acc[mt][nt][2] + b0, v3 = acc[mt][nt][3] + b1;
                if (relu) {
                    v0 = fmaxf(v0, 0.f); v1 = fmaxf(v1, 0.f);
                    v2 = fmaxf(v2, 0.f); v3 = fmaxf(v3, 0.f);
                }
                if (useC1) {
                    if (ra < M)
                        *(float2*)(C1 + (size_t)ra * ldc + oc) = make_float2(v0, v1);
                    if (ra + 8 < M)
                        *(float2*)(C1 + (size_t)(ra + 8) * ldc + oc) = make_float2(v2, v3);
                } else if (C0h) {
                    if (ra < M)
                        *(__half2*)(C0h + (size_t)ra * ldc + oc) = __floats2half2_rn(v0, v1);
                    if (ra + 8 < M)
                        *(__half2*)(C0h + (size_t)(ra + 8) * ldc + oc) = __floats2half2_rn(v2, v3);
                } else {
                    if (ra < M) {
                        *(float2*)(C0 + (size_t)ra * ldc + oc) = make_float2(v0, v1);
                        if (Sh) {
                            __nv_bfloat16 h0 = __float2bfloat16(v0), h1 = __float2bfloat16(v1);
                            *(__nv_bfloat162*)(Sh + (size_t)ra * ldc + oc) = make_bfloat162(h0, h1);
                            *(__nv_bfloat162*)(Sl + (size_t)ra * ldc + oc) =
                                make_bfloat162(__float2bfloat16(v0 - __bfloat162float(h0)),
                                               __float2bfloat16(v1 - __bfloat162float(h1)));
                        }
                    }
                    if (ra + 8 < M) {
                        *(float2*)(C0 + (size_t)(ra + 8) * ldc + oc) = make_float2(v2, v3);
                        if (Sh) {
                            __nv_bfloat16 h2 = __float2bfloat16(v2), h3 = __float2bfloat16(v3);
                            *(__nv_bfloat162*)(Sh + (size_t)(ra + 8) * ldc + oc) = make_bfloat162(h2, h3);
                            *(__nv_bfloat162*)(Sl + (size_t)(ra + 8) * ldc + oc) =
                                make_bfloat162(__float2bfloat16(v2 - __bfloat162float(h2)),
                                               __float2bfloat16(v3 - __bfloat162float(h3)));
                        }
                    }
                }
            }
        }
    }
}

// ---------------- per-node score dots: dv = at.xl, dr = at.xr ----------------
__global__ void dots_kernel(const float* __restrict__ att) {
    int node = (blockIdx.x * blockDim.x + threadIdx.x) >> 5;
    if (node >= Nn) return;
    int lane = threadIdx.x & 31;
    float4 a = *(const float4*)(att + lane * 4);
    uint2 rw = *(const uint2*)(g_xlh + (size_t)node * Hh + lane * 4);
    float2 lo = __half22float2(*(__half2*)&rw.x);
    float2 hi = __half22float2(*(__half2*)&rw.y);
    float dv = a.x * lo.x + a.y * lo.y + a.z * hi.x + a.w * hi.y;
    float4 xrv = *(const float4*)(g_xr + (size_t)node * Hh + lane * 4);
    float dr = a.x * xrv.x + a.y * xrv.y + a.z * xrv.z + a.w * xrv.w;
    #pragma unroll
    for (int off = 16; off; off >>= 1) {
        dv += __shfl_xor_sync(0xffffffffu, dv, off);
        dr += __shfl_xor_sync(0xffffffffu, dr, off);
    }
    if (lane == 0) { g_dv[node] = dv; g_dr[node] = dr; }
}

// ---------------- fused GATv2: 4 deg-matched nodes/warp, 8 lanes/node --------
// score t = 0.6*(dv[u]+dr[d]) + 0.4*(at . |xl[u]+xr[d]|)  (exact leaky identity)
// no online max (scores O(1)-bounded); exp(-inf)=0 absorbs padding.
__global__ void gat_kernel(const float* __restrict__ att, const float* __restrict__ bg,
                           const float* __restrict__ lng, const float* __restrict__ lnb,
                           int use_res, int do_relu)
{
    int gwarp = (blockIdx.x * blockDim.x + threadIdx.x) >> 5;
    if (gwarp >= Nn / 4) return;
    int lane = threadIdx.x & 31;
    int grp  = lane >> 3;                   // 0..3
    int sl   = lane & 7;                    // 0..7
    int node = g_order[gwarp * 4 + grp];
    int fo   = sl * 16;

    float xr[16], at[16], acc[16];
    #pragma unroll
    for (int c = 0; c < 4; ++c) {
        *(float4*)&xr[c * 4] = *(const float4*)(g_xr + (size_t)node * Hh + fo + c * 4);
        *(float4*)&at[c * 4] = *(const float4*)(att + fo + c * 4);
    }
    #pragma unroll
    for (int k = 0; k < 16; ++k) acc[k] = 0.f;

    int beg = g_rowptr[node];
    int deg = g_rowptr[node + 1] - beg;
    int mdeg = deg;
    mdeg = max(mdeg, __shfl_xor_sync(0xffffffffu, mdeg, 8));
    mdeg = max(mdeg, __shfl_xor_sync(0xffffffffu, mdeg, 16));
    float dr = g_dr[node];

    float z = 0.f;

    for (int jj = 0; jj < mdeg; jj += 2) {
        float av[2][16];
        float tv[2], t1[2];
        bool  vq[2];
        #pragma unroll
        for (int q = 0; q < 2; ++q) {
            vq[q] = (jj + q) < deg;
            int u = g_esrc[vq[q] ? (beg + jj + q) : beg];
            const uint4* xp = (const uint4*)(g_xlh + ((unsigned)u << 7) + fo);
            uint4 r0 = xp[0], r1 = xp[1];
            float2 f;
            f = __half22float2(*(__half2*)&r0.x); av[q][0]  = f.x; av[q][1]  = f.y;
            f = __half22float2(*(__half2*)&r0.y); av[q][2]  = f.x; av[q][3]  = f.y;
            f = __half22float2(*(__half2*)&r0.z); av[q][4]  = f.x; av[q][5]  = f.y;
            f = __half22float2(*(__half2*)&r0.w); av[q][6]  = f.x; av[q][7]  = f.y;
            f = __half22float2(*(__half2*)&r1.x); av[q][8]  = f.x; av[q][9]  = f.y;
            f = __half22float2(*(__half2*)&r1.y); av[q][10] = f.x; av[q][11] = f.y;
            f = __half22float2(*(__half2*)&r1.z); av[q][12] = f.x; av[q][13] = f.y;
            f = __half22float2(*(__half2*)&r1.w); av[q][14] = f.x; av[q][15] = f.y;
            float t2 = 0.f;
            #pragma unroll
            for (int k = 0; k < 16; ++k) {
                float e = av[q][k] + xr[k];
                t2 = fmaf(at[k], fabsf(e), t2);
            }
            tv[q] = t2;
            t1[q] = g_dv[u] + dr;
        }
        #pragma unroll
        for (int off = 4; off; off >>= 1) {
            tv[0] += __shfl_xor_sync(0xffffffffu, tv[0], off);
            tv[1] += __shfl_xor_sync(0xffffffffu, tv[1], off);
        }
        #pragma unroll
        for (int q = 0; q < 2; ++q) {
            float t = fmaf(0.4f, tv[q], 0.6f * t1[q]);
            float w = __expf(vq[q] ? t : -INFINITY);
            z += w;
            #pragma unroll
            for (int k = 0; k < 16; ++k) acc[k] = fmaf(w, av[q][k], acc[k]);
        }
    }

    float inv = __fdividef(1.f, z);
    float o[16];
    #pragma unroll
    for (int c = 0; c < 4; ++c) {
        float4 bv = *(const float4*)(bg + fo + c * 4);
        o[c * 4 + 0] = acc[c * 4 + 0] * inv + bv.x;
        o[c * 4 + 1] = acc[c * 4 + 1] * inv + bv.y;
        o[c * 4 + 2] = acc[c * 4 + 2] * inv + bv.z;
        o[c * 4 + 3] = acc[c * 4 + 3] * inv + bv.w;
    }
    if (use_res) {
        #pragma unroll
        for (int c = 0; c < 4; ++c) {
            float4 rv = *(const float4*)(g_h + (size_t)node * Hh + fo + c * 4);
            o[c * 4 + 0] += rv.x; o[c * 4 + 1] += rv.y;
            o[c * 4 + 2] += rv.z; o[c * 4 + 3] += rv.w;
        }
    }

    float s1 = 0.f, s2 = 0.f;
    #pragma unroll
    for (int k = 0; k < 16; ++k) { s1 += o[k]; s2 += o[k] * o[k]; }
    #pragma unroll
    for (int off = 4; off; off >>= 1) {
        s1 += __shfl_xor_sync(0xffffffffu, s1, off);
        s2 += __shfl_xor_sync(0xffffffffu, s2, off);
    }
    float mean = s1 * (1.f / Hh);
    float var  = s2 * (1.f / Hh) - mean * mean;
    float rs = rsqrtf(var + LNEPS);
    #pragma unroll
    for (int c = 0; c < 4; ++c) {
        float4 gv = *(const float4*)(lng + fo + c * 4);
        float4 bv = *(const float4*)(lnb + fo + c * 4);
        o[c * 4 + 0] = (o[c * 4 + 0] - mean) * rs * gv.x + bv.x;
        o[c * 4 + 1] = (o[c * 4 + 1] - mean) * rs * gv.y + bv.y;
        o[c * 4 + 2] = (o[c * 4 + 2] - mean) * rs * gv.z + bv.z;
        o[c * 4 + 3] = (o[c * 4 + 3] - mean) * rs * gv.w + bv.w;
    }
    if (do_relu) {
        #pragma unroll
        for (int k = 0; k < 16; ++k) o[k] = fmaxf(o[k], 0.f);
    }

    size_t base = (size_t)node * Hh + fo;
    #pragma unroll
    for (int c = 0; c < 4; ++c)
        *(float4*)(g_h + base + c * 4) = *(float4*)&o[c * 4];
    #pragma unroll
    for (int k = 0; k < 16; k += 2) {
        __nv_bfloat16 h0 = __float2bfloat16(o[k]), h1 = __float2bfloat16(o[k + 1]);
        *(__nv_bfloat162*)(g_hs_h + base + k) = make_bfloat162(h0, h1);
        *(__nv_bfloat162*)(g_hs_l + base + k) =
            make_bfloat162(__float2bfloat16(o[k] - __bfloat162float(h0)),
                           __float2bfloat16(o[k + 1] - __bfloat162float(h1)));
    }
}

// ---------------- final [N,64] @ [64,2] + b2 ---------------------------------
__global__ void mlp_out_kernel(const float* __restrict__ W2, const float* __restrict__ b2,
                               float* __restrict__ out)
{
    int warp = (blockIdx.x * blockDim.x + threadIdx.x) >> 5;
    if (warp >= Nn) return;
    int lane = threadIdx.x & 31;
    float v0 = g_xl[(size_t)warp * 64 + lane];
    float v1 = g_xl[(size_t)warp * 64 + lane + 32];
    float p0 = v0 * W2[lane * 2 + 0] + v1 * W2[(lane + 32) * 2 + 0];
    float p1 = v0 * W2[lane * 2 + 1] + v1 * W2[(lane + 32) * 2 + 1];
    #pragma unroll
    for (int off = 16; off; off >>= 1) {
        p0 += __shfl_xor_sync(0xffffffffu, p0, off);
        p1 += __shfl_xor_sync(0xffffffffu, p1, off);
    }
    if (lane == 0) {
        out[(size_t)warp * 2 + 0] = p0 + b2[0];
        out[(size_t)warp * 2 + 1] = p1 + b2[1];
    }
}

// -----------------------------------------------------------------------------
extern "C" void kernel_launch(void* const* d_in, const int* in_sizes, int n_in,
                              void* d_out, int out_size)
{
    (void)in_sizes; (void)n_in; (void)out_size;
    const float* x    = (const float*)d_in[0];
    const int*   ei   = (const int*)  d_in[1];
    const float* Win  = (const float*)d_in[2];
    const float* bin_ = (const float*)d_in[3];
    const float* Wl   = (const float*)d_in[4];
    const float* bl   = (const float*)d_in[5];
    const float* Wr   = (const float*)d_in[6];
    const float* br   = (const float*)d_in[7];
    const float* att  = (const float*)d_in[8];
    const float* bg   = (const float*)d_in[9];
    const float* lng  = (const float*)d_in[10];
    const float* lnb  = (const float*)d_in[11];
    const float* W1   = (const float*)d_in[12];
    const float* b1   = (const float*)d_in[13];
    const float* W2   = (const float*)d_in[14];
    const float* b2   = (const float*)d_in[15];
    float* out = (float*)d_out;

    const int* srcp = ei;
    const int* dstp = ei + Ee;

    float *p_h, *p_xl, *p_xr;
    __half* p_xlh;
    __nv_bfloat16 *p_bwh, *p_bwl, *p_xsh, *p_xsl, *p_hsh, *p_hsl;
    cudaGetSymbolAddress((void**)&p_h,   g_h);
    cudaGetSymbolAddress((void**)&p_xl,  g_xl);
    cudaGetSymbolAddress((void**)&p_xr,  g_xr);
    cudaGetSymbolAddress((void**)&p_xlh, g_xlh);
    cudaGetSymbolAddress((void**)&p_bwh, g_bwh);
    cudaGetSymbolAddress((void**)&p_bwl, g_bwl);
    cudaGetSymbolAddress((void**)&p_xsh, g_xs_h);
    cudaGetSymbolAddress((void**)&p_xsl, g_xs_l);
    cudaGetSymbolAddress((void**)&p_hsh, g_hs_h);
    cudaGetSymbolAddress((void**)&p_hsl, g_hs_l);

    const int GX = (Nn + 127) / 128;   // 391
    const int BIG = 1 << 30;
    const int GAT_BLOCKS = (Nn / 4 * 32 + 255) / 256;   // 1563
    const int DOT_BLOCKS = (Nn * 32 + 255) / 256;       // 6250

    cudaFuncSetAttribute(gemm3_kernel, cudaFuncAttributeMaxDynamicSharedMemorySize, SMEM_B);

    // 0: weight convert (+deg init, +dbin reset)   1: x convert (+hist)
    wconvert_kernel<<<(TOTW + 255) / 256, 256>>>(Win, Wl, Wr, W1);
    xconvert_kernel<<<(Nn * FIN + 255) / 256, 256>>>(x, dstp);
    // 2: input projection h = relu(x @ Win + bin), emits split-bf16 h
    gemm3_kernel<<<dim3(GX, 1), 256, SMEM_B>>>(p_xsh, p_xsl, FIN,
                                       p_bwh + OFF_WIN, p_bwl + OFF_WIN,
                                       bin_, bin_, p_h, p_h, nullptr, p_hsh, p_hsl,
                                       Nn, FIN, Hh, BIG, Hh, 1);
    // 3: layer-0 fused Wl||Wr GEMM (ncu-profiled slot); xl -> fp16, xr -> fp32
    gemm3_kernel<<<dim3(GX, 2), 256, SMEM_B>>>(p_hsh, p_hsl, Hh,
                                       p_bwh + OFF_WLR, p_bwl + OFF_WLR,
                                       bl, br, nullptr, p_xr, p_xlh, nullptr, nullptr,
                                       Nn, Hh, 256, Hh, Hh, 0);
    // 4-6: degree bucket sort
    dsort_hist_kernel<<<(Nn + 255) / 256, 256>>>();
    dsort_scan_kernel<<<1, 32>>>();
    dsort_scatter_kernel<<<(Nn + 255) / 256, 256>>>();
    // 7-9: CSR build
    scan1_kernel<<<NB_SCAN, 1024>>>();
    scan3_kernel<<<NB_SCAN, 1024>>>();
    scatter_kernel<<<(EN + 255) / 256, 256>>>(srcp, dstp);
    // 10-11: layer-0 dots + attention
    dots_kernel<<<DOT_BLOCKS, 256>>>(att);
    gat_kernel<<<GAT_BLOCKS, 256>>>(att, bg, lng, lnb, 0, 1);
    // layers 1..2
    for (int i = 1; i < 3; ++i) {
        gemm3_kernel<<<dim3(GX, 2), 256, SMEM_B>>>(p_hsh, p_hsl, Hh,
                                           p_bwh + OFF_WLR + (size_t)i * 256 * 128,
                                           p_bwl + OFF_WLR + (size_t)i * 256 * 128,
                                           bl + (size_t)i * Hh, br + (size_t)i * Hh,
                                           nullptr, p_xr, p_xlh, nullptr, nullptr,
                                           Nn, Hh, 256, Hh, Hh, 0);
        dots_kernel<<<DOT_BLOCKS, 256>>>(att + (size_t)i * Hh);
        gat_kernel<<<GAT_BLOCKS, 256>>>(att + (size_t)i * Hh, bg + (size_t)i * Hh,
                                        lng + (size_t)i * Hh, lnb + (size_t)i * Hh,
                                        1, (i < 2) ? 1 : 0);
    }
    // output MLP: t1 = relu(h @ W1 + b1) -> g_xl [N,64] (fp32), then @ W2 + b2
    gemm3_kernel<<<dim3(GX, 1), 256, SMEM_B>>>(p_hsh, p_hsl, Hh,
                                       p_bwh + OFF_W1, p_bwl + OFF_W1,
                                       b1, b1, p_xl, p_xl, nullptr, nullptr, nullptr,
                                       Nn, Hh, 64, BIG, 64, 1);
    mlp_out_kernel<<<(Nn * 32 + 255) / 256, 256>>>(W2, b2, out);
}

// round 13
// speedup vs baseline: 1.1593x; 1.1593x over previous
#include <cuda_runtime.h>
#include <cuda_bf16.h>
#include <cuda_fp16.h>
#include <math.h>
#include <stdint.h>

#define Nn   50000
#define Ee   800000
#define EN   (Ee + Nn)
#define Hh   128
#define FIN  64
#define NEGS 0.2f
#define LNEPS 1e-5f
#define NB_SCAN 49   // ceil(50000/1024)

#define OFF_WIN 0
#define OFF_WLR 8192                     // 128*64
#define OFF_W1  (8192 + 3 * 256 * 128)   // 106496
#define TOTW    (OFF_W1 + 64 * 128)      // 114688

// ---------------- scratch (static device globals; no allocation) -------------
__device__ float g_h [Nn * Hh];
__device__ float g_xl[Nn * Hh];          // t1 scratch for MLP
__device__ float g_xr[Nn * Hh];
__device__ __align__(16) __half g_xlh[Nn * Hh];   // xl in fp16 for the gather
__device__ int   g_deg[Nn];
__device__ int   g_incl[Nn];
__device__ int   g_rowptr[Nn + 1];
__device__ int   g_cursor[Nn + 1];
__device__ int   g_esrc[EN];
__device__ int   g_bsums[64];
__device__ int   g_dbin[64];             // degree-bucket counts
__device__ int   g_dcur[64];             // degree-bucket cursors
__device__ int   g_order[Nn];            // nodes sorted by degree
__device__ __align__(16) __nv_bfloat16 g_bwh[TOTW];      // weights hi, n-major
__device__ __align__(16) __nv_bfloat16 g_bwl[TOTW];      // weights lo, n-major
__device__ __align__(16) __nv_bfloat16 g_xs_h[Nn * FIN]; // x split hi
__device__ __align__(16) __nv_bfloat16 g_xs_l[Nn * FIN]; // x split lo
__device__ __align__(16) __nv_bfloat16 g_hs_h[Nn * Hh];  // h split hi
__device__ __align__(16) __nv_bfloat16 g_hs_l[Nn * Hh];  // h split lo

// ---------------- weight split/convert (fp32 -> bf16 hi/lo, n-major) ---------
__global__ void wconvert_kernel(const float* __restrict__ Win, const float* __restrict__ Wl,
                                const float* __restrict__ Wr, const float* __restrict__ W1)
{
    int i = blockIdx.x * blockDim.x + threadIdx.x;
    if (i < Nn) g_deg[i] = 1;               // self-loop deg init (fused)
    if (i < 64) g_dbin[i] = 0;              // degree-bucket reset (fused)
    if (i >= TOTW) return;
    float v;
    if (i < OFF_WLR) {                       // Win [64,128] -> n-major [128][64]
        int n = i >> 6, k = i & 63;
        v = Win[k * 128 + n];
    } else if (i < OFF_W1) {                 // Wl||Wr per layer -> [256][128]
        int j = i - OFF_WLR;
        int l = j >> 15, r = j & 32767;
        int n = r >> 7, k = r & 127;
        v = (n < 128) ? Wl[l * 16384 + k * 128 + n]
                      : Wr[l * 16384 + k * 128 + (n - 128)];
    } else {                                 // W1 [128,64] -> n-major [64][128]
        int j = i - OFF_W1;
        int n = j >> 7, k = j & 127;
        v = W1[k * 64 + n];
    }
    __nv_bfloat16 hi = __float2bfloat16(v);
    g_bwh[i] = hi;
    g_bwl[i] = __float2bfloat16(v - __bfloat162float(hi));
}

// x split + edge histogram (fused: grid covers Nn*FIN >= Ee)
__global__ void xconvert_kernel(const float* __restrict__ x, const int* __restrict__ dst) {
    int i = blockIdx.x * blockDim.x + threadIdx.x;
    if (i < Nn * FIN) {
        float v = x[i];
        __nv_bfloat16 hi = __float2bfloat16(v);
        g_xs_h[i] = hi;
        g_xs_l[i] = __float2bfloat16(v - __bfloat162float(hi));
    }
    if (i < Ee) atomicAdd(&g_deg[dst[i]], 1);
}

// ---------------- degree bucket sort (balances GAT warp pairing) -------------
__global__ void dsort_hist_kernel() {
    __shared__ int sb[64];
    if (threadIdx.x < 64) sb[threadIdx.x] = 0;
    __syncthreads();
    int i = blockIdx.x * blockDim.x + threadIdx.x;
    if (i < Nn) {
        int b = min(g_deg[i] - 1, 63);
        atomicAdd(&sb[b], 1);
    }
    __syncthreads();
    if (threadIdx.x < 64 && sb[threadIdx.x])
        atomicAdd(&g_dbin[threadIdx.x], sb[threadIdx.x]);
}

__global__ void dsort_scan_kernel() {
    if (threadIdx.x == 0) {
        int run = 0;
        for (int j = 0; j < 64; ++j) { int t = g_dbin[j]; g_dcur[j] = run; run += t; }
    }
}

__global__ void dsort_scatter_kernel() {
    int i = blockIdx.x * blockDim.x + threadIdx.x;
    if (i < Nn) {
        int b = min(g_deg[i] - 1, 63);
        int p = atomicAdd(&g_dcur[b], 1);
        g_order[p] = i;
    }
}

// ---------------- CSR build --------------------------------------------------
__global__ void scan1_kernel() {
    __shared__ int sm[1024];
    int i = blockIdx.x * 1024 + threadIdx.x;
    int v = (i < Nn) ? g_deg[i] : 0;
    sm[threadIdx.x] = v;
    __syncthreads();
    #pragma unroll
    for (int off = 1; off < 1024; off <<= 1) {
        int t = 0;
        if ((int)threadIdx.x >= off) t = sm[threadIdx.x - off];
        __syncthreads();
        sm[threadIdx.x] += t;
        __syncthreads();
    }
    if (i < Nn) g_incl[i] = sm[threadIdx.x];
    if (threadIdx.x == 1023) g_bsums[blockIdx.x] = sm[1023];
}

__global__ void scan3_kernel() {
    __shared__ int base_s;
    if (threadIdx.x == 0) {
        int b = 0;
        for (int j = 0; j < (int)blockIdx.x; ++j) b += g_bsums[j];
        base_s = b;
    }
    __syncthreads();
    int i = blockIdx.x * 1024 + threadIdx.x;
    if (i < Nn) {
        int val = g_incl[i] + base_s;
        g_rowptr[i + 1] = val;
        g_cursor[i + 1] = val;
        if (i == 0) { g_rowptr[0] = 0; g_cursor[0] = 0; }
    }
}

__global__ void scatter_kernel(const int* __restrict__ src, const int* __restrict__ dst) {
    int e = blockIdx.x * blockDim.x + threadIdx.x;
    if (e < EN) {
        int s, d;
        if (e < Ee) { s = src[e]; d = dst[e]; }
        else        { s = d = e - Ee; }
        int p = atomicAdd(&g_cursor[d], 1);
        g_esrc[p] = s;
    }
}

// ---------------- bf16x3 tensor-core GEMM (32x64 warp tiles, cp.async) -------
__device__ __forceinline__ void mma16816(float* c, const unsigned* a, const unsigned* b) {
    asm volatile(
        "mma.sync.aligned.m16n8k16.row.col.f32.bf16.bf16.f32 "
        "{%0,%1,%2,%3},{%4,%5,%6,%7},{%8,%9},{%0,%1,%2,%3};"
        : "+f"(c[0]), "+f"(c[1]), "+f"(c[2]), "+f"(c[3])
        : "r"(a[0]), "r"(a[1]), "r"(a[2]), "r"(a[3]), "r"(b[0]), "r"(b[1]));
}

__device__ __forceinline__ void ldsm4(unsigned* r, const __nv_bfloat16* p) {
    unsigned addr = (unsigned)__cvta_generic_to_shared(p);
    asm volatile("ldmatrix.sync.aligned.m8n8.x4.shared.b16 {%0,%1,%2,%3},[%4];"
                 : "=r"(r[0]), "=r"(r[1]), "=r"(r[2]), "=r"(r[3]) : "r"(addr));
}

__device__ __forceinline__ void cpa16(uint32_t dst, const void* src, uint32_t srcsz) {
    asm volatile("cp.async.ca.shared.global [%0], [%1], 16, %2;"
                 :: "r"(dst), "l"(src), "r"(srcsz) : "memory");
}
#define CPA_COMMIT() asm volatile("cp.async.commit_group;" ::: "memory")

#define ARR_E   (128 * 40)
#define BUF_E   (4 * ARR_E)
#define SMEM_B  (2 * BUF_E * 2)          // bytes = 81920

extern __shared__ __nv_bfloat16 smbf[];

__global__ void __launch_bounds__(256, 2) gemm3_kernel(
    const __nv_bfloat16* __restrict__ Ah, const __nv_bfloat16* __restrict__ Al, int lda,
    const __nv_bfloat16* __restrict__ Bh, const __nv_bfloat16* __restrict__ Bl,
    const float* __restrict__ bias0, const float* __restrict__ bias1,
    float* __restrict__ C0, float* __restrict__ C1, __half* __restrict__ C0h,
    __nv_bfloat16* __restrict__ Sh, __nv_bfloat16* __restrict__ Sl,
    int M, int K, int Nvalid, int nsplit, int ldc, int relu)
{
    const int tid = threadIdx.x;
    const int lane = tid & 31;
    const int wid = tid >> 5;
    const int warp_m = wid >> 1;
    const int warp_n = wid & 1;
    const int mrow = lane & 7;
    const int mat  = lane >> 3;

    const int row0 = blockIdx.x * 128;
    const int col0 = blockIdx.y * 128;

    float acc[2][8][4];
    #pragma unroll
    for (int a = 0; a < 2; ++a)
        #pragma unroll
        for (int b = 0; b < 8; ++b)
            #pragma unroll
            for (int c = 0; c < 4; ++c) acc[a][b][c] = 0.f;

    const int r  = tid >> 1;     // 0..127
    const int hf = tid & 1;
    const uint32_t smaddr = (uint32_t)__cvta_generic_to_shared(smbf);
    const uint32_t arow_sz = ((row0 + r) < M) ? 16u : 0u;
    const uint32_t brow_sz = ((col0 + r) < Nvalid) ? 16u : 0u;
    const int nk = K >> 5;

    #define STAGE(ck, buf) do {                                                      \
        int kk_ = (ck) * 32;                                                         \
        uint32_t base_ = smaddr + (uint32_t)((buf) * BUF_E) * 2u;                    \
        uint32_t doff_ = (uint32_t)(r * 40 + hf * 16) * 2u;                          \
        const __nv_bfloat16* pah_ = Ah + (size_t)(row0 + r) * lda + kk_ + hf * 16;   \
        const __nv_bfloat16* pal_ = Al + (size_t)(row0 + r) * lda + kk_ + hf * 16;   \
        cpa16(base_ + doff_,                    pah_,     arow_sz);                  \
        cpa16(base_ + doff_ + 16,               pah_ + 8, arow_sz);                  \
        cpa16(base_ + ARR_E * 2 + doff_,        pal_,     arow_sz);                  \
        cpa16(base_ + ARR_E * 2 + doff_ + 16,   pal_ + 8, arow_sz);                  \
        const __nv_bfloat16* pbh_ = Bh + (size_t)(col0 + r) * K + kk_ + hf * 16;     \
        const __nv_bfloat16* pbl_ = Bl + (size_t)(col0 + r) * K + kk_ + hf * 16;     \
        cpa16(base_ + ARR_E * 4 + doff_,        pbh_,     brow_sz);                  \
        cpa16(base_ + ARR_E * 4 + doff_ + 16,   pbh_ + 8, brow_sz);                  \
        cpa16(base_ + ARR_E * 6 + doff_,        pbl_,     brow_sz);                  \
        cpa16(base_ + ARR_E * 6 + doff_ + 16,   pbl_ + 8, brow_sz);                  \
        CPA_COMMIT();                                                                \
    } while (0)

    STAGE(0, 0);

    for (int ci = 0; ci < nk; ++ci) {
        if (ci + 1 < nk) {
            STAGE(ci + 1, (ci + 1) & 1);
            asm volatile("cp.async.wait_group 1;" ::: "memory");
        } else {
            asm volatile("cp.async.wait_group 0;" ::: "memory");
        }
        __syncthreads();

        const __nv_bfloat16* sAh = smbf + (ci & 1) * BUF_E;
        const __nv_bfloat16* sAl = sAh + ARR_E;
        const __nv_bfloat16* sBh = sAh + 2 * ARR_E;
        const __nv_bfloat16* sBl = sAh + 3 * ARR_E;

        #pragma unroll
        for (int ks = 0; ks < 2; ++ks) {
            const int ck = ks * 16;
            unsigned ah[2][4], al[2][4];
            #pragma unroll
            for (int mt = 0; mt < 2; ++mt) {
                int ar  = warp_m * 32 + mt * 16 + ((mat & 1) << 3) + mrow;
                int acl = ck + ((mat >> 1) << 3);
                ldsm4(ah[mt], sAh + ar * 40 + acl);
                ldsm4(al[mt], sAl + ar * 40 + acl);
            }
            #pragma unroll
            for (int p = 0; p < 4; ++p) {
                unsigned bh4[4], bl4[4];
                int bn  = warp_n * 64 + p * 16 + ((mat >> 1) << 3) + mrow;
                int bcl = ck + ((mat & 1) << 3);
                ldsm4(bh4, sBh + bn * 40 + bcl);
                ldsm4(bl4, sBl + bn * 40 + bcl);
                #pragma unroll
                for (int half = 0; half < 2; ++half) {
                    int nt = p * 2 + half;
                    #pragma unroll
                    for (int mt = 0; mt < 2; ++mt) {
                        mma16816(acc[mt][nt], ah[mt], &bh4[half * 2]);
                        mma16816(acc[mt][nt], al[mt], &bh4[half * 2]);
                        mma16816(acc[mt][nt], ah[mt], &bl4[half * 2]);
                    }
                }
            }
        }
        __syncthreads();
    }

    // ---- epilogue ----
    const float* bp;
    int colbase;
    int useC1 = (col0 >= nsplit);
    if (useC1) { bp = bias1; colbase = col0 - nsplit; }
    else       { bp = bias0; colbase = col0; }

    const int g = lane >> 2, qt = lane & 3;
    #pragma unroll
    for (int mt = 0; mt < 2; ++mt) {
        #pragma unroll
        for (int nt = 0; nt < 8; ++nt) {
            int gcol = col0 + warp_n * 64 + nt * 8 + 2 * qt;
            if (gcol < Nvalid) {
                int oc = colbase + warp_n * 64 + nt * 8 + 2 * qt;
                float b0 = bp[oc], b1 = bp[oc + 1];
                int ra = row0 + warp_m * 32 + mt * 16 + g;
                float v0 = acc[mt][nt][0] + b0, v1 = acc[mt][nt][1] + b1;
                float v2 = acc[mt][nt][2] + b0, v3 = acc[mt][nt][3] + b1;
                if (relu) {
                    v0 = fmaxf(v0, 0.f); v1 = fmaxf(v1, 0.f);
                    v2 = fmaxf(v2, 0.f); v3 = fmaxf(v3, 0.f);
                }
                if (useC1) {
                    if (ra < M)
                        *(float2*)(C1 + (size_t)ra * ldc + oc) = make_float2(v0, v1);
                    if (ra + 8 < M)
                        *(float2*)(C1 + (size_t)(ra + 8) * ldc + oc) = make_float2(v2, v3);
                } else if (C0h) {
                    if (ra < M)
                        *(__half2*)(C0h + (size_t)ra * ldc + oc) = __floats2half2_rn(v0, v1);
                    if (ra + 8 < M)
                        *(__half2*)(C0h + (size_t)(ra + 8) * ldc + oc) = __floats2half2_rn(v2, v3);
                } else {
                    if (ra < M) {
                        *(float2*)(C0 + (size_t)ra * ldc + oc) = make_float2(v0, v1);
                        if (Sh) {
                            __nv_bfloat16 h0 = __float2bfloat16(v0), h1 = __float2bfloat16(v1);
                            *(__nv_bfloat162*)(Sh + (size_t)ra * ldc + oc) = make_bfloat162(h0, h1);
                            *(__nv_bfloat162*)(Sl + (size_t)ra * ldc + oc) =
                                make_bfloat162(__float2bfloat16(v0 - __bfloat162float(h0)),
                                               __float2bfloat16(v1 - __bfloat162float(h1)));
                        }
                    }
                    if (ra + 8 < M) {
                        *(float2*)(C0 + (size_t)(ra + 8) * ldc + oc) = make_float2(v2, v3);
                        if (Sh) {
                            __nv_bfloat16 h2 = __float2bfloat16(v2), h3 = __float2bfloat16(v3);
                            *(__nv_bfloat162*)(Sh + (size_t)(ra + 8) * ldc + oc) = make_bfloat162(h2, h3);
                            *(__nv_bfloat162*)(Sl + (size_t)(ra + 8) * ldc + oc) =
                                make_bfloat162(__float2bfloat16(v2 - __bfloat162float(h2)),
                                               __float2bfloat16(v3 - __bfloat162float(h3)));
                        }
                    }
                }
            }
        }
    }
}

// ---------------- fused GATv2: 2 deg-matched nodes/warp, 16 lanes/node -------
// fp16 uint4 gather; leaky via exact identity 0.6e+0.4|e| (two FMA chains);
// no online max (scores O(1)-bounded); exp(-inf)=0 absorbs padding.
__global__ void gat_kernel(const float* __restrict__ att, const float* __restrict__ bg,
                           const float* __restrict__ lng, const float* __restrict__ lnb,
                           int use_res, int do_relu)
{
    int gwarp = (blockIdx.x * blockDim.x + threadIdx.x) >> 5;
    if (gwarp >= Nn / 2) return;
    int lane = threadIdx.x & 31;
    int grp  = lane >> 4;
    int sl   = lane & 15;
    int node = g_order[gwarp * 2 + grp];    // degree-matched pairing
    int fo   = sl * 8;

    float xr[8], at[8], acc[8];
    *(float4*)&xr[0] = *(const float4*)(g_xr + (size_t)node * Hh + fo);
    *(float4*)&xr[4] = *(const float4*)(g_xr + (size_t)node * Hh + fo + 4);
    *(float4*)&at[0] = *(const float4*)(att + fo);
    *(float4*)&at[4] = *(const float4*)(att + fo + 4);
    #pragma unroll
    for (int k = 0; k < 8; ++k) acc[k] = 0.f;

    int beg = g_rowptr[node], end = g_rowptr[node + 1];
    int deg = end - beg;
    int mdeg = max(deg, __shfl_xor_sync(0xffffffffu, deg, 16));

    float z = 0.f;

    for (int jj = 0; jj < mdeg; jj += 4) {
        float av[4][8];
        float tv[4];
        #pragma unroll
        for (int q = 0; q < 4; ++q) {
            bool valid = (jj + q) < deg;
            int u = g_esrc[valid ? (beg + jj + q) : beg];
            uint4 rw = *(const uint4*)(g_xlh + ((unsigned)u << 7) + fo);
            float2 f;
            f = __half22float2(*(__half2*)&rw.x); av[q][0] = f.x; av[q][1] = f.y;
            f = __half22float2(*(__half2*)&rw.y); av[q][2] = f.x; av[q][3] = f.y;
            f = __half22float2(*(__half2*)&rw.z); av[q][4] = f.x; av[q][5] = f.y;
            f = __half22float2(*(__half2*)&rw.w); av[q][6] = f.x; av[q][7] = f.y;
            float t1 = 0.f, t2 = 0.f;
            #pragma unroll
            for (int k = 0; k < 8; ++k) {
                float e = av[q][k] + xr[k];
                t1 = fmaf(at[k], e, t1);
                t2 = fmaf(at[k], fabsf(e), t2);
            }
            float t = fmaf(0.4f, t2, 0.6f * t1);   // exact leaky identity
            tv[q] = valid ? t : -INFINITY;
        }
        #pragma unroll
        for (int off = 8; off; off >>= 1) {
            #pragma unroll
            for (int q = 0; q < 4; ++q)
                tv[q] += __shfl_xor_sync(0xffffffffu, tv[q], off);
        }
        #pragma unroll
        for (int q = 0; q < 4; ++q) {
            float w = __expf(tv[q]);        // exp(-inf) = 0 for pad slots
            z += w;
            #pragma unroll
            for (int k = 0; k < 8; ++k) acc[k] += w * av[q][k];
        }
    }

    float inv = __fdividef(1.f, z);
    float o[8];
    {
        float4 b0 = *(const float4*)(bg + fo);
        float4 b1 = *(const float4*)(bg + fo + 4);
        o[0] = acc[0] * inv + b0.x; o[1] = acc[1] * inv + b0.y;
        o[2] = acc[2] * inv + b0.z; o[3] = acc[3] * inv + b0.w;
        o[4] = acc[4] * inv + b1.x; o[5] = acc[5] * inv + b1.y;
        o[6] = acc[6] * inv + b1.z; o[7] = acc[7] * inv + b1.w;
    }
    if (use_res) {
        float4 r0 = *(const float4*)(g_h + (size_t)node * Hh + fo);
        float4 r1 = *(const float4*)(g_h + (size_t)node * Hh + fo + 4);
        o[0] += r0.x; o[1] += r0.y; o[2] += r0.z; o[3] += r0.w;
        o[4] += r1.x; o[5] += r1.y; o[6] += r1.z; o[7] += r1.w;
    }

    float s1 = 0.f, s2 = 0.f;
    #pragma unroll
    for (int k = 0; k < 8; ++k) { s1 += o[k]; s2 += o[k] * o[k]; }
    #pragma unroll
    for (int off = 8; off; off >>= 1) {
        s1 += __shfl_xor_sync(0xffffffffu, s1, off);
        s2 += __shfl_xor_sync(0xffffffffu, s2, off);
    }
    float mean = s1 * (1.f / Hh);
    float var  = s2 * (1.f / Hh) - mean * mean;
    float rs = rsqrtf(var + LNEPS);
    {
        float4 g0 = *(const float4*)(lng + fo);
        float4 g1 = *(const float4*)(lng + fo + 4);
        float4 b0 = *(const float4*)(lnb + fo);
        float4 b1 = *(const float4*)(lnb + fo + 4);
        float gv[8] = {g0.x, g0.y, g0.z, g0.w, g1.x, g1.y, g1.z, g1.w};
        float bv[8] = {b0.x, b0.y, b0.z, b0.w, b1.x, b1.y, b1.z, b1.w};
        #pragma unroll
        for (int k = 0; k < 8; ++k) {
            o[k] = (o[k] - mean) * rs * gv[k] + bv[k];
            if (do_relu) o[k] = fmaxf(o[k], 0.f);
        }
    }

    size_t base = (size_t)node * Hh + fo;
    *(float4*)(g_h + base)     = make_float4(o[0], o[1], o[2], o[3]);
    *(float4*)(g_h + base + 4) = make_float4(o[4], o[5], o[6], o[7]);
    #pragma unroll
    for (int k = 0; k < 8; k += 2) {
        __nv_bfloat16 h0 = __float2bfloat16(o[k]), h1 = __float2bfloat16(o[k + 1]);
        *(__nv_bfloat162*)(g_hs_h + base + k) = make_bfloat162(h0, h1);
        *(__nv_bfloat162*)(g_hs_l + base + k) =
            make_bfloat162(__float2bfloat16(o[k] - __bfloat162float(h0)),
                           __float2bfloat16(o[k + 1] - __bfloat162float(h1)));
    }
}

// ---------------- final [N,64] @ [64,2] + b2 ---------------------------------
__global__ void mlp_out_kernel(const float* __restrict__ W2, const float* __restrict__ b2,
                               float* __restrict__ out)
{
    int warp = (blockIdx.x * blockDim.x + threadIdx.x) >> 5;
    if (warp >= Nn) return;
    int lane = threadIdx.x & 31;
    float v0 = g_xl[(size_t)warp * 64 + lane];
    float v1 = g_xl[(size_t)warp * 64 + lane + 32];
    float p0 = v0 * W2[lane * 2 + 0] + v1 * W2[(lane + 32) * 2 + 0];
    float p1 = v0 * W2[lane * 2 + 1] + v1 * W2[(lane + 32) * 2 + 1];
    #pragma unroll
    for (int off = 16; off; off >>= 1) {
        p0 += __shfl_xor_sync(0xffffffffu, p0, off);
        p1 += __shfl_xor_sync(0xffffffffu, p1, off);
    }
    if (lane == 0) {
        out[(size_t)warp * 2 + 0] = p0 + b2[0];
        out[(size_t)warp * 2 + 1] = p1 + b2[1];
    }
}

// -----------------------------------------------------------------------------
extern "C" void kernel_launch(void* const* d_in, const int* in_sizes, int n_in,
                              void* d_out, int out_size)
{
    (void)in_sizes; (void)n_in; (void)out_size;
    const float* x    = (const float*)d_in[0];
    const int*   ei   = (const int*)  d_in[1];
    const float* Win  = (const float*)d_in[2];
    const float* bin_ = (const float*)d_in[3];
    const float* Wl   = (const float*)d_in[4];
    const float* bl   = (const float*)d_in[5];
    const float* Wr   = (const float*)d_in[6];
    const float* br   = (const float*)d_in[7];
    const float* att  = (const float*)d_in[8];
    const float* bg   = (const float*)d_in[9];
    const float* lng  = (const float*)d_in[10];
    const float* lnb  = (const float*)d_in[11];
    const float* W1   = (const float*)d_in[12];
    const float* b1   = (const float*)d_in[13];
    const float* W2   = (const float*)d_in[14];
    const float* b2   = (const float*)d_in[15];
    float* out = (float*)d_out;

    const int* srcp = ei;
    const int* dstp = ei + Ee;

    float *p_h, *p_xl, *p_xr;
    __half* p_xlh;
    __nv_bfloat16 *p_bwh, *p_bwl, *p_xsh, *p_xsl, *p_hsh, *p_hsl;
    cudaGetSymbolAddress((void**)&p_h,   g_h);
    cudaGetSymbolAddress((void**)&p_xl,  g_xl);
    cudaGetSymbolAddress((void**)&p_xr,  g_xr);
    cudaGetSymbolAddress((void**)&p_xlh, g_xlh);
    cudaGetSymbolAddress((void**)&p_bwh, g_bwh);
    cudaGetSymbolAddress((void**)&p_bwl, g_bwl);
    cudaGetSymbolAddress((void**)&p_xsh, g_xs_h);
    cudaGetSymbolAddress((void**)&p_xsl, g_xs_l);
    cudaGetSymbolAddress((void**)&p_hsh, g_hs_h);
    cudaGetSymbolAddress((void**)&p_hsl, g_hs_l);

    const int GX = (Nn + 127) / 128;   // 391
    const int BIG = 1 << 30;
    const int GAT_BLOCKS = (Nn / 2 * 32) / 256;   // 3125

    cudaFuncSetAttribute(gemm3_kernel, cudaFuncAttributeMaxDynamicSharedMemorySize, SMEM_B);

    // 0: weight convert (+deg init, +dbin reset)   1: x convert (+hist)
    wconvert_kernel<<<(TOTW + 255) / 256, 256>>>(Win, Wl, Wr, W1);
    xconvert_kernel<<<(Nn * FIN + 255) / 256, 256>>>(x, dstp);
    // 2: input projection h = relu(x @ Win + bin), emits split-bf16 h
    gemm3_kernel<<<dim3(GX, 1), 256, SMEM_B>>>(p_xsh, p_xsl, FIN,
                                       p_bwh + OFF_WIN, p_bwl + OFF_WIN,
                                       bin_, bin_, p_h, p_h, nullptr, p_hsh, p_hsl,
                                       Nn, FIN, Hh, BIG, Hh, 1);
    // 3: layer-0 fused Wl||Wr GEMM (ncu-profiled slot); xl -> fp16, xr -> fp32
    gemm3_kernel<<<dim3(GX, 2), 256, SMEM_B>>>(p_hsh, p_hsl, Hh,
                                       p_bwh + OFF_WLR, p_bwl + OFF_WLR,
                                       bl, br, nullptr, p_xr, p_xlh, nullptr, nullptr,
                                       Nn, Hh, 256, Hh, Hh, 0);
    // 4-6: degree bucket sort
    dsort_hist_kernel<<<(Nn + 255) / 256, 256>>>();
    dsort_scan_kernel<<<1, 32>>>();
    dsort_scatter_kernel<<<(Nn + 255) / 256, 256>>>();
    // 7-9: CSR build
    scan1_kernel<<<NB_SCAN, 1024>>>();
    scan3_kernel<<<NB_SCAN, 1024>>>();
    scatter_kernel<<<(EN + 255) / 256, 256>>>(srcp, dstp);
    // 10: layer-0 attention
    gat_kernel<<<GAT_BLOCKS, 256>>>(att, bg, lng, lnb, 0, 1);
    // layers 1..2
    for (int i = 1; i < 3; ++i) {
        gemm3_kernel<<<dim3(GX, 2), 256, SMEM_B>>>(p_hsh, p_hsl, Hh,
                                           p_bwh + OFF_WLR + (size_t)i * 256 * 128,
                                           p_bwl + OFF_WLR + (size_t)i * 256 * 128,
                                           bl + (size_t)i * Hh, br + (size_t)i * Hh,
                                           nullptr, p_xr, p_xlh, nullptr, nullptr,
                                           Nn, Hh, 256, Hh, Hh, 0);
        gat_kernel<<<GAT_BLOCKS, 256>>>(att + (size_t)i * Hh, bg + (size_t)i * Hh,
                                        lng + (size_t)i * Hh, lnb + (size_t)i * Hh,
                                        1, (i < 2) ? 1 : 0);
    }
    // output MLP: t1 = relu(h @ W1 + b1) -> g_xl [N,64] (fp32), then @ W2 + b2
    gemm3_kernel<<<dim3(GX, 1), 256, SMEM_B>>>(p_hsh, p_hsl, Hh,
                                       p_bwh + OFF_W1, p_bwl + OFF_W1,
                                       b1, b1, p_xl, p_xl, nullptr, nullptr, nullptr,
                                       Nn, Hh, 64, BIG, 64, 1);
    mlp_out_kernel<<<(Nn * 32 + 255) / 256, 256>>>(W2, b2, out);
}

// round 14
// speedup vs baseline: 1.1824x; 1.0199x over previous
#include <cuda_runtime.h>
#include <cuda_bf16.h>
#include <cuda_fp16.h>
#include <math.h>
#include <stdint.h>

#define Nn   50000
#define Ee   800000
#define EN   (Ee + Nn)
#define Hh   128
#define FIN  64
#define NEGS 0.2f
#define LNEPS 1e-5f
#define NB_SCAN 49   // ceil(50000/1024)

#define OFF_WIN 0
#define OFF_WLR 8192                     // 128*64
#define OFF_W1  (8192 + 3 * 256 * 128)   // 106496
#define TOTW    (OFF_W1 + 64 * 128)      // 114688

// ---------------- scratch (static device globals; no allocation) -------------
__device__ float g_h [Nn * Hh];
__device__ float g_xl[Nn * Hh];          // t1 scratch for MLP
__device__ float g_xr[Nn * Hh];
__device__ __align__(16) __half g_xlh[Nn * Hh];   // xl in fp16 for the gather
__device__ int   g_deg[Nn];
__device__ int   g_incl[Nn];
__device__ int   g_rowptr[Nn + 1];
__device__ int   g_cursor[Nn + 1];
__device__ int   g_esrc[EN];
__device__ int   g_bsums[64];
__device__ int   g_dbin[64];             // degree-bucket counts
__device__ int   g_dcur[64];             // degree-bucket cursors
__device__ int   g_order[Nn];            // nodes sorted by degree
__device__ __align__(16) __nv_bfloat16 g_bwh[TOTW];      // weights hi, n-major
__device__ __align__(16) __nv_bfloat16 g_bwl[TOTW];      // weights lo, n-major
__device__ __align__(16) __nv_bfloat16 g_xs_h[Nn * FIN]; // x split hi
__device__ __align__(16) __nv_bfloat16 g_xs_l[Nn * FIN]; // x split lo
__device__ __align__(16) __nv_bfloat16 g_hs_h[Nn * Hh];  // h split hi
__device__ __align__(16) __nv_bfloat16 g_hs_l[Nn * Hh];  // h split lo

// ---------------- weight split/convert (fp32 -> bf16 hi/lo, n-major) ---------
__global__ void wconvert_kernel(const float* __restrict__ Win, const float* __restrict__ Wl,
                                const float* __restrict__ Wr, const float* __restrict__ W1)
{
    int i = blockIdx.x * blockDim.x + threadIdx.x;
    if (i < Nn) g_deg[i] = 1;               // self-loop deg init (fused)
    if (i < 64) g_dbin[i] = 0;              // degree-bucket reset (fused)
    if (i >= TOTW) return;
    float v;
    if (i < OFF_WLR) {                       // Win [64,128] -> n-major [128][64]
        int n = i >> 6, k = i & 63;
        v = Win[k * 128 + n];
    } else if (i < OFF_W1) {                 // Wl||Wr per layer -> [256][128]
        int j = i - OFF_WLR;
        int l = j >> 15, r = j & 32767;
        int n = r >> 7, k = r & 127;
        v = (n < 128) ? Wl[l * 16384 + k * 128 + n]
                      : Wr[l * 16384 + k * 128 + (n - 128)];
    } else {                                 // W1 [128,64] -> n-major [64][128]
        int j = i - OFF_W1;
        int n = j >> 7, k = j & 127;
        v = W1[k * 64 + n];
    }
    __nv_bfloat16 hi = __float2bfloat16(v);
    g_bwh[i] = hi;
    g_bwl[i] = __float2bfloat16(v - __bfloat162float(hi));
}

// x split + edge histogram (fused: grid covers Nn*FIN >= Ee)
__global__ void xconvert_kernel(const float* __restrict__ x, const int* __restrict__ dst) {
    int i = blockIdx.x * blockDim.x + threadIdx.x;
    if (i < Nn * FIN) {
        float v = x[i];
        __nv_bfloat16 hi = __float2bfloat16(v);
        g_xs_h[i] = hi;
        g_xs_l[i] = __float2bfloat16(v - __bfloat162float(hi));
    }
    if (i < Ee) atomicAdd(&g_deg[dst[i]], 1);
}

// ---------------- CSR build (+ fused degree bucket sort) ---------------------
// scan1: block-local inclusive prefix of degrees + degree-bucket histogram
__global__ void scan1_kernel() {
    __shared__ int sm[1024];
    __shared__ int sb[64];
    if (threadIdx.x < 64) sb[threadIdx.x] = 0;
    int i = blockIdx.x * 1024 + threadIdx.x;
    int v = (i < Nn) ? g_deg[i] : 0;
    sm[threadIdx.x] = v;
    __syncthreads();
    if (i < Nn) atomicAdd(&sb[min(v - 1, 63)], 1);
    #pragma unroll
    for (int off = 1; off < 1024; off <<= 1) {
        int t = 0;
        if ((int)threadIdx.x >= off) t = sm[threadIdx.x - off];
        __syncthreads();
        sm[threadIdx.x] += t;
        __syncthreads();
    }
    if (i < Nn) g_incl[i] = sm[threadIdx.x];
    if (threadIdx.x == 1023) g_bsums[blockIdx.x] = sm[1023];
    if (threadIdx.x < 64 && sb[threadIdx.x])
        atomicAdd(&g_dbin[threadIdx.x], sb[threadIdx.x]);
}

// scan3: rowptr from block sums; block 0 also scans the degree buckets
__global__ void scan3_kernel() {
    __shared__ int base_s;
    if (threadIdx.x == 0) {
        int b = 0;
        for (int j = 0; j < (int)blockIdx.x; ++j) b += g_bsums[j];
        base_s = b;
    }
    if (blockIdx.x == 0 && threadIdx.x == 1) {
        int run = 0;
        for (int j = 0; j < 64; ++j) { int t = g_dbin[j]; g_dcur[j] = run; run += t; }
    }
    __syncthreads();
    int i = blockIdx.x * 1024 + threadIdx.x;
    if (i < Nn) {
        int val = g_incl[i] + base_s;
        g_rowptr[i + 1] = val;
        g_cursor[i + 1] = val;
        if (i == 0) { g_rowptr[0] = 0; g_cursor[0] = 0; }
    }
}

// scatter: CSR edge scatter + fused degree-order scatter (grid EN >= Nn)
__global__ void scatter_kernel(const int* __restrict__ src, const int* __restrict__ dst) {
    int e = blockIdx.x * blockDim.x + threadIdx.x;
    if (e < EN) {
        int s, d;
        if (e < Ee) { s = src[e]; d = dst[e]; }
        else        { s = d = e - Ee; }
        int p = atomicAdd(&g_cursor[d], 1);
        g_esrc[p] = s;
    }
    if (e < Nn) {
        int b = min(g_deg[e] - 1, 63);
        int p = atomicAdd(&g_dcur[b], 1);
        g_order[p] = e;
    }
}

// ---------------- bf16x3 tensor-core GEMM (32x64 warp tiles, cp.async) -------
__device__ __forceinline__ void mma16816(float* c, const unsigned* a, const unsigned* b) {
    asm volatile(
        "mma.sync.aligned.m16n8k16.row.col.f32.bf16.bf16.f32 "
        "{%0,%1,%2,%3},{%4,%5,%6,%7},{%8,%9},{%0,%1,%2,%3};"
        : "+f"(c[0]), "+f"(c[1]), "+f"(c[2]), "+f"(c[3])
        : "r"(a[0]), "r"(a[1]), "r"(a[2]), "r"(a[3]), "r"(b[0]), "r"(b[1]));
}

__device__ __forceinline__ void ldsm4(unsigned* r, const __nv_bfloat16* p) {
    unsigned addr = (unsigned)__cvta_generic_to_shared(p);
    asm volatile("ldmatrix.sync.aligned.m8n8.x4.shared.b16 {%0,%1,%2,%3},[%4];"
                 : "=r"(r[0]), "=r"(r[1]), "=r"(r[2]), "=r"(r[3]) : "r"(addr));
}

__device__ __forceinline__ void cpa16(uint32_t dst, const void* src, uint32_t srcsz) {
    asm volatile("cp.async.ca.shared.global [%0], [%1], 16, %2;"
                 :: "r"(dst), "l"(src), "r"(srcsz) : "memory");
}
#define CPA_COMMIT() asm volatile("cp.async.commit_group;" ::: "memory")

#define ARR_E   (128 * 40)
#define BUF_E   (4 * ARR_E)
#define SMEM_B  (2 * BUF_E * 2)          // bytes = 81920

extern __shared__ __nv_bfloat16 smbf[];

__global__ void __launch_bounds__(256, 2) gemm3_kernel(
    const __nv_bfloat16* __restrict__ Ah, const __nv_bfloat16* __restrict__ Al, int lda,
    const __nv_bfloat16* __restrict__ Bh, const __nv_bfloat16* __restrict__ Bl,
    const float* __restrict__ bias0, const float* __restrict__ bias1,
    float* __restrict__ C0, float* __restrict__ C1, __half* __restrict__ C0h,
    __nv_bfloat16* __restrict__ Sh, __nv_bfloat16* __restrict__ Sl,
    int M, int K, int Nvalid, int nsplit, int ldc, int relu)
{
    const int tid = threadIdx.x;
    const int lane = tid & 31;
    const int wid = tid >> 5;
    const int warp_m = wid >> 1;
    const int warp_n = wid & 1;
    const int mrow = lane & 7;
    const int mat  = lane >> 3;

    const int row0 = blockIdx.x * 128;
    const int col0 = blockIdx.y * 128;
    const bool wvalid = (col0 + warp_n * 64) < Nvalid;   // warp-tile has live cols

    float acc[2][8][4];
    #pragma unroll
    for (int a = 0; a < 2; ++a)
        #pragma unroll
        for (int b = 0; b < 8; ++b)
            #pragma unroll
            for (int c = 0; c < 4; ++c) acc[a][b][c] = 0.f;

    const int r  = tid >> 1;     // 0..127
    const int hf = tid & 1;
    const uint32_t smaddr = (uint32_t)__cvta_generic_to_shared(smbf);
    const uint32_t arow_sz = ((row0 + r) < M) ? 16u : 0u;
    const uint32_t brow_sz = ((col0 + r) < Nvalid) ? 16u : 0u;
    const int nk = K >> 5;

    #define STAGE(ck, buf) do {                                                      \
        int kk_ = (ck) * 32;                                                         \
        uint32_t base_ = smaddr + (uint32_t)((buf) * BUF_E) * 2u;                    \
        uint32_t doff_ = (uint32_t)(r * 40 + hf * 16) * 2u;                          \
        const __nv_bfloat16* pah_ = Ah + (size_t)(row0 + r) * lda + kk_ + hf * 16;   \
        const __nv_bfloat16* pal_ = Al + (size_t)(row0 + r) * lda + kk_ + hf * 16;   \
        cpa16(base_ + doff_,                    pah_,     arow_sz);                  \
        cpa16(base_ + doff_ + 16,               pah_ + 8, arow_sz);                  \
        cpa16(base_ + ARR_E * 2 + doff_,        pal_,     arow_sz);                  \
        cpa16(base_ + ARR_E * 2 + doff_ + 16,   pal_ + 8, arow_sz);                  \
        const __nv_bfloat16* pbh_ = Bh + (size_t)(col0 + r) * K + kk_ + hf * 16;     \
        const __nv_bfloat16* pbl_ = Bl + (size_t)(col0 + r) * K + kk_ + hf * 16;     \
        cpa16(base_ + ARR_E * 4 + doff_,        pbh_,     brow_sz);                  \
        cpa16(base_ + ARR_E * 4 + doff_ + 16,   pbh_ + 8, brow_sz);                  \
        cpa16(base_ + ARR_E * 6 + doff_,        pbl_,     brow_sz);                  \
        cpa16(base_ + ARR_E * 6 + doff_ + 16,   pbl_ + 8, brow_sz);                  \
        CPA_COMMIT();                                                                \
    } while (0)

    STAGE(0, 0);

    for (int ci = 0; ci < nk; ++ci) {
        if (ci + 1 < nk) {
            STAGE(ci + 1, (ci + 1) & 1);
            asm volatile("cp.async.wait_group 1;" ::: "memory");
        } else {
            asm volatile("cp.async.wait_group 0;" ::: "memory");
        }
        __syncthreads();

        if (wvalid) {
            const __nv_bfloat16* sAh = smbf + (ci & 1) * BUF_E;
            const __nv_bfloat16* sAl = sAh + ARR_E;
            const __nv_bfloat16* sBh = sAh + 2 * ARR_E;
            const __nv_bfloat16* sBl = sAh + 3 * ARR_E;

            #pragma unroll
            for (int ks = 0; ks < 2; ++ks) {
                const int ck = ks * 16;
                unsigned ah[2][4], al[2][4];
                #pragma unroll
                for (int mt = 0; mt < 2; ++mt) {
                    int ar  = warp_m * 32 + mt * 16 + ((mat & 1) << 3) + mrow;
                    int acl = ck + ((mat >> 1) << 3);
                    ldsm4(ah[mt], sAh + ar * 40 + acl);
                    ldsm4(al[mt], sAl + ar * 40 + acl);
                }
                #pragma unroll
                for (int p = 0; p < 4; ++p) {
                    unsigned bh4[4], bl4[4];
                    int bn  = warp_n * 64 + p * 16 + ((mat >> 1) << 3) + mrow;
                    int bcl = ck + ((mat & 1) << 3);
                    ldsm4(bh4, sBh + bn * 40 + bcl);
                    ldsm4(bl4, sBl + bn * 40 + bcl);
                    #pragma unroll
                    for (int half = 0; half < 2; ++half) {
                        int nt = p * 2 + half;
                        #pragma unroll
                        for (int mt = 0; mt < 2; ++mt) {
                            mma16816(acc[mt][nt], ah[mt], &bh4[half * 2]);
                            mma16816(acc[mt][nt], al[mt], &bh4[half * 2]);
                            mma16816(acc[mt][nt], ah[mt], &bl4[half * 2]);
                        }
                    }
                }
            }
        }
        __syncthreads();
    }

    // ---- epilogue ----
    if (!wvalid) return;
    const float* bp;
    int colbase;
    int useC1 = (col0 >= nsplit);
    if (useC1) { bp = bias1; colbase = col0 - nsplit; }
    else       { bp = bias0; colbase = col0; }

    const int g = lane >> 2, qt = lane & 3;
    #pragma unroll
    for (int mt = 0; mt < 2; ++mt) {
        #pragma unroll
        for (int nt = 0; nt < 8; ++nt) {
            int gcol = col0 + warp_n * 64 + nt * 8 + 2 * qt;
            if (gcol < Nvalid) {
                int oc = colbase + warp_n * 64 + nt * 8 + 2 * qt;
                float b0 = bp[oc], b1 = bp[oc + 1];
                int ra = row0 + warp_m * 32 + mt * 16 + g;
                float v0 = acc[mt][nt][0] + b0, v1 = acc[mt][nt][1] + b1;
                float v2 = acc[mt][nt][2] + b0, v3 = acc[mt][nt][3] + b1;
                if (relu) {
                    v0 = fmaxf(v0, 0.f); v1 = fmaxf(v1, 0.f);
                    v2 = fmaxf(v2, 0.f); v3 = fmaxf(v3, 0.f);
                }
                if (useC1) {
                    if (ra < M)
                        *(float2*)(C1 + (size_t)ra * ldc + oc) = make_float2(v0, v1);
                    if (ra + 8 < M)
                        *(float2*)(C1 + (size_t)(ra + 8) * ldc + oc) = make_float2(v2, v3);
                } else if (C0h) {
                    if (ra < M)
                        *(__half2*)(C0h + (size_t)ra * ldc + oc) = __floats2half2_rn(v0, v1);
                    if (ra + 8 < M)
                        *(__half2*)(C0h + (size_t)(ra + 8) * ldc + oc) = __floats2half2_rn(v2, v3);
                } else {
                    if (ra < M) {
                        *(float2*)(C0 + (size_t)ra * ldc + oc) = make_float2(v0, v1);
                        if (Sh) {
                            __nv_bfloat16 h0 = __float2bfloat16(v0), h1 = __float2bfloat16(v1);
                            *(__nv_bfloat162*)(Sh + (size_t)ra * ldc + oc) = make_bfloat162(h0, h1);
                            *(__nv_bfloat162*)(Sl + (size_t)ra * ldc + oc) =
                                make_bfloat162(__float2bfloat16(v0 - __bfloat162float(h0)),
                                               __float2bfloat16(v1 - __bfloat162float(h1)));
                        }
                    }
                    if (ra + 8 < M) {
                        *(float2*)(C0 + (size_t)(ra + 8) * ldc + oc) = make_float2(v2, v3);
                        if (Sh) {
                            __nv_bfloat16 h2 = __float2bfloat16(v2), h3 = __float2bfloat16(v3);
                            *(__nv_bfloat162*)(Sh + (size_t)(ra + 8) * ldc + oc) = make_bfloat162(h2, h3);
                            *(__nv_bfloat162*)(Sl + (size_t)(ra + 8) * ldc + oc) =
                                make_bfloat162(__float2bfloat16(v2 - __bfloat162float(h2)),
                                               __float2bfloat16(v3 - __bfloat162float(h3)));
                        }
                    }
                }
            }
        }
    }
}

// ---------------- fused GATv2: 2 deg-matched nodes/warp, 16 lanes/node -------
// fp16 uint4 gather; leaky via exact identity 0.6e+0.4|e| (two FMA chains);
// no online max (scores O(1)-bounded); exp(-inf)=0 absorbs padding.
__global__ void gat_kernel(const float* __restrict__ att, const float* __restrict__ bg,
                           const float* __restrict__ lng, const float* __restrict__ lnb,
                           int use_res, int do_relu)
{
    int gwarp = (blockIdx.x * blockDim.x + threadIdx.x) >> 5;
    if (gwarp >= Nn / 2) return;
    int lane = threadIdx.x & 31;
    int grp  = lane >> 4;
    int sl   = lane & 15;
    int node = g_order[gwarp * 2 + grp];    // degree-matched pairing
    int fo   = sl * 8;

    float xr[8], at[8], acc[8];
    *(float4*)&xr[0] = *(const float4*)(g_xr + (size_t)node * Hh + fo);
    *(float4*)&xr[4] = *(const float4*)(g_xr + (size_t)node * Hh + fo + 4);
    *(float4*)&at[0] = *(const float4*)(att + fo);
    *(float4*)&at[4] = *(const float4*)(att + fo + 4);
    #pragma unroll
    for (int k = 0; k < 8; ++k) acc[k] = 0.f;

    int beg = g_rowptr[node], end = g_rowptr[node + 1];
    int deg = end - beg;
    int mdeg = max(deg, __shfl_xor_sync(0xffffffffu, deg, 16));

    float z = 0.f;

    for (int jj = 0; jj < mdeg; jj += 4) {
        float av[4][8];
        float tv[4];
        #pragma unroll
        for (int q = 0; q < 4; ++q) {
            bool valid = (jj + q) < deg;
            int u = g_esrc[valid ? (beg + jj + q) : beg];
            uint4 rw = *(const uint4*)(g_xlh + ((unsigned)u << 7) + fo);
            float2 f;
            f = __half22float2(*(__half2*)&rw.x); av[q][0] = f.x; av[q][1] = f.y;
            f = __half22float2(*(__half2*)&rw.y); av[q][2] = f.x; av[q][3] = f.y;
            f = __half22float2(*(__half2*)&rw.z); av[q][4] = f.x; av[q][5] = f.y;
            f = __half22float2(*(__half2*)&rw.w); av[q][6] = f.x; av[q][7] = f.y;
            float t1 = 0.f, t2 = 0.f;
            #pragma unroll
            for (int k = 0; k < 8; ++k) {
                float e = av[q][k] + xr[k];
                t1 = fmaf(at[k], e, t1);
                t2 = fmaf(at[k], fabsf(e), t2);
            }
            float t = fmaf(0.4f, t2, 0.6f * t1);   // exact leaky identity
            tv[q] = valid ? t : -INFINITY;
        }
        #pragma unroll
        for (int off = 8; off; off >>= 1) {
            #pragma unroll
            for (int q = 0; q < 4; ++q)
                tv[q] += __shfl_xor_sync(0xffffffffu, tv[q], off);
        }
        #pragma unroll
        for (int q = 0; q < 4; ++q) {
            float w = __expf(tv[q]);        // exp(-inf) = 0 for pad slots
            z += w;
            #pragma unroll
            for (int k = 0; k < 8; ++k) acc[k] += w * av[q][k];
        }
    }

    float inv = __fdividef(1.f, z);
    float o[8];
    {
        float4 b0 = *(const float4*)(bg + fo);
        float4 b1 = *(const float4*)(bg + fo + 4);
        o[0] = acc[0] * inv + b0.x; o[1] = acc[1] * inv + b0.y;
        o[2] = acc[2] * inv + b0.z; o[3] = acc[3] * inv + b0.w;
        o[4] = acc[4] * inv + b1.x; o[5] = acc[5] * inv + b1.y;
        o[6] = acc[6] * inv + b1.z; o[7] = acc[7] * inv + b1.w;
    }
    if (use_res) {
        float4 r0 = *(const float4*)(g_h + (size_t)node * Hh + fo);
        float4 r1 = *(const float4*)(g_h + (size_t)node * Hh + fo + 4);
        o[0] += r0.x; o[1] += r0.y; o[2] += r0.z; o[3] += r0.w;
        o[4] += r1.x; o[5] += r1.y; o[6] += r1.z; o[7] += r1.w;
    }

    float s1 = 0.f, s2 = 0.f;
    #pragma unroll
    for (int k = 0; k < 8; ++k) { s1 += o[k]; s2 += o[k] * o[k]; }
    #pragma unroll
    for (int off = 8; off; off >>= 1) {
        s1 += __shfl_xor_sync(0xffffffffu, s1, off);
        s2 += __shfl_xor_sync(0xffffffffu, s2, off);
    }
    float mean = s1 * (1.f / Hh);
    float var  = s2 * (1.f / Hh) - mean * mean;
    float rs = rsqrtf(var + LNEPS);
    {
        float4 g0 = *(const float4*)(lng + fo);
        float4 g1 = *(const float4*)(lng + fo + 4);
        float4 b0 = *(const float4*)(lnb + fo);
        float4 b1 = *(const float4*)(lnb + fo + 4);
        float gv[8] = {g0.x, g0.y, g0.z, g0.w, g1.x, g1.y, g1.z, g1.w};
        float bv[8] = {b0.x, b0.y, b0.z, b0.w, b1.x, b1.y, b1.z, b1.w};
        #pragma unroll
        for (int k = 0; k < 8; ++k) {
            o[k] = (o[k] - mean) * rs * gv[k] + bv[k];
            if (do_relu) o[k] = fmaxf(o[k], 0.f);
        }
    }

    size_t base = (size_t)node * Hh + fo;
    *(float4*)(g_h + base)     = make_float4(o[0], o[1], o[2], o[3]);
    *(float4*)(g_h + base + 4) = make_float4(o[4], o[5], o[6], o[7]);
    #pragma unroll
    for (int k = 0; k < 8; k += 2) {
        __nv_bfloat16 h0 = __float2bfloat16(o[k]), h1 = __float2bfloat16(o[k + 1]);
        *(__nv_bfloat162*)(g_hs_h + base + k) = make_bfloat162(h0, h1);
        *(__nv_bfloat162*)(g_hs_l + base + k) =
            make_bfloat162(__float2bfloat16(o[k] - __bfloat162float(h0)),
                           __float2bfloat16(o[k + 1] - __bfloat162float(h1)));
    }
}

// ---------------- final [N,64] @ [64,2] + b2 ---------------------------------
__global__ void mlp_out_kernel(const float* __restrict__ W2, const float* __restrict__ b2,
                               float* __restrict__ out)
{
    int warp = (blockIdx.x * blockDim.x + threadIdx.x) >> 5;
    if (warp >= Nn) return;
    int lane = threadIdx.x & 31;
    float v0 = g_xl[(size_t)warp * 64 + lane];
    float v1 = g_xl[(size_t)warp * 64 + lane + 32];
    float p0 = v0 * W2[lane * 2 + 0] + v1 * W2[(lane + 32) * 2 + 0];
    float p1 = v0 * W2[lane * 2 + 1] + v1 * W2[(lane + 32) * 2 + 1];
    #pragma unroll
    for (int off = 16; off; off >>= 1) {
        p0 += __shfl_xor_sync(0xffffffffu, p0, off);
        p1 += __shfl_xor_sync(0xffffffffu, p1, off);
    }
    if (lane == 0) {
        out[(size_t)warp * 2 + 0] = p0 + b2[0];
        out[(size_t)warp * 2 + 1] = p1 + b2[1];
    }
}

// -----------------------------------------------------------------------------
extern "C" void kernel_launch(void* const* d_in, const int* in_sizes, int n_in,
                              void* d_out, int out_size)
{
    (void)in_sizes; (void)n_in; (void)out_size;
    const float* x    = (const float*)d_in[0];
    const int*   ei   = (const int*)  d_in[1];
    const float* Win  = (const float*)d_in[2];
    const float* bin_ = (const float*)d_in[3];
    const float* Wl   = (const float*)d_in[4];
    const float* bl   = (const float*)d_in[5];
    const float* Wr   = (const float*)d_in[6];
    const float* br   = (const float*)d_in[7];
    const float* att  = (const float*)d_in[8];
    const float* bg   = (const float*)d_in[9];
    const float* lng  = (const float*)d_in[10];
    const float* lnb  = (const float*)d_in[11];
    const float* W1   = (const float*)d_in[12];
    const float* b1   = (const float*)d_in[13];
    const float* W2   = (const float*)d_in[14];
    const float* b2   = (const float*)d_in[15];
    float* out = (float*)d_out;

    const int* srcp = ei;
    const int* dstp = ei + Ee;

    float *p_h, *p_xl, *p_xr;
    __half* p_xlh;
    __nv_bfloat16 *p_bwh, *p_bwl, *p_xsh, *p_xsl, *p_hsh, *p_hsl;
    cudaGetSymbolAddress((void**)&p_h,   g_h);
    cudaGetSymbolAddress((void**)&p_xl,  g_xl);
    cudaGetSymbolAddress((void**)&p_xr,  g_xr);
    cudaGetSymbolAddress((void**)&p_xlh, g_xlh);
    cudaGetSymbolAddress((void**)&p_bwh, g_bwh);
    cudaGetSymbolAddress((void**)&p_bwl, g_bwl);
    cudaGetSymbolAddress((void**)&p_xsh, g_xs_h);
    cudaGetSymbolAddress((void**)&p_xsl, g_xs_l);
    cudaGetSymbolAddress((void**)&p_hsh, g_hs_h);
    cudaGetSymbolAddress((void**)&p_hsl, g_hs_l);

    const int GX = (Nn + 127) / 128;   // 391
    const int BIG = 1 << 30;
    const int GAT_BLOCKS = (Nn / 2 * 32) / 256;   // 3125

    cudaFuncSetAttribute(gemm3_kernel, cudaFuncAttributeMaxDynamicSharedMemorySize, SMEM_B);

    // 0: weight convert (+deg init, +dbin reset)   1: x convert (+hist)
    wconvert_kernel<<<(TOTW + 255) / 256, 256>>>(Win, Wl, Wr, W1);
    xconvert_kernel<<<(Nn * FIN + 255) / 256, 256>>>(x, dstp);
    // 2: input projection h = relu(x @ Win + bin), emits split-bf16 h
    gemm3_kernel<<<dim3(GX, 1), 256, SMEM_B>>>(p_xsh, p_xsl, FIN,
                                       p_bwh + OFF_WIN, p_bwl + OFF_WIN,
                                       bin_, bin_, p_h, p_h, nullptr, p_hsh, p_hsl,
                                       Nn, FIN, Hh, BIG, Hh, 1);
    // 3: layer-0 fused Wl||Wr GEMM (ncu-profiled slot); xl -> fp16, xr -> fp32
    gemm3_kernel<<<dim3(GX, 2), 256, SMEM_B>>>(p_hsh, p_hsl, Hh,
                                       p_bwh + OFF_WLR, p_bwl + OFF_WLR,
                                       bl, br, nullptr, p_xr, p_xlh, nullptr, nullptr,
                                       Nn, Hh, 256, Hh, Hh, 0);
    // 4-6: CSR build (+fused degree sort)
    scan1_kernel<<<NB_SCAN, 1024>>>();
    scan3_kernel<<<NB_SCAN, 1024>>>();
    scatter_kernel<<<(EN + 255) / 256, 256>>>(srcp, dstp);
    // 7: layer-0 attention
    gat_kernel<<<GAT_BLOCKS, 256>>>(att, bg, lng, lnb, 0, 1);
    // layers 1..2
    for (int i = 1; i < 3; ++i) {
        gemm3_kernel<<<dim3(GX, 2), 256, SMEM_B>>>(p_hsh, p_hsl, Hh,
                                           p_bwh + OFF_WLR + (size_t)i * 256 * 128,
                                           p_bwl + OFF_WLR + (size_t)i * 256 * 128,
                                           bl + (size_t)i * Hh, br + (size_t)i * Hh,
                                           nullptr, p_xr, p_xlh, nullptr, nullptr,
                                           Nn, Hh, 256, Hh, Hh, 0);
        gat_kernel<<<GAT_BLOCKS, 256>>>(att + (size_t)i * Hh, bg + (size_t)i * Hh,
                                        lng + (size_t)i * Hh, lnb + (size_t)i * Hh,
                                        1, (i < 2) ? 1 : 0);
    }
    // output MLP: t1 = relu(h @ W1 + b1) -> g_xl [N,64] (fp32), then @ W2 + b2
    gemm3_kernel<<<dim3(GX, 1), 256, SMEM_B>>>(p_hsh, p_hsl, Hh,
                                       p_bwh + OFF_W1, p_bwl + OFF_W1,
                                       b1, b1, p_xl, p_xl, nullptr, nullptr, nullptr,
                                       Nn, Hh, 64, BIG, 64, 1);
    mlp_out_kernel<<<(Nn * 32 + 255) / 256, 256>>>(W2, b2, out);
}

// round 15
// speedup vs baseline: 1.2290x; 1.0394x over previous
#include <cuda_runtime.h>
#include <cuda_bf16.h>
#include <cuda_fp16.h>
#include <math.h>
#include <stdint.h>

#define Nn   50000
#define Ee   800000
#define EN   (Ee + Nn)
#define Hh   128
#define FIN  64
#define NEGS 0.2f
#define LNEPS 1e-5f
#define NB_SCAN 49   // ceil(50000/1024)

#define OFF_WIN 0
#define OFF_WLR 8192                     // 128*64
#define OFF_W1  (8192 + 3 * 256 * 128)   // 106496
#define TOTW    (OFF_W1 + 64 * 128)      // 114688

// ---------------- scratch (static device globals; no allocation) -------------
__device__ float g_h [Nn * Hh];
__device__ float g_xl[Nn * Hh];          // t1 scratch for MLP
__device__ float g_xr[Nn * Hh];
__device__ __align__(16) __half g_xlh[Nn * Hh];   // xl in fp16 for the gather
__device__ int   g_deg[Nn];
__device__ int   g_incl[Nn];
__device__ int   g_rowptr[Nn + 1];
__device__ int   g_cursor[Nn + 1];
__device__ int   g_esrc[EN];
__device__ int   g_bsums[64];
__device__ int   g_dbin[64];             // degree-bucket counts
__device__ int   g_dcur[64];             // degree-bucket cursors
__device__ int   g_order[Nn];            // nodes sorted by degree
__device__ __align__(16) __nv_bfloat16 g_bwh[TOTW];      // weights hi, n-major
__device__ __align__(16) __nv_bfloat16 g_bwl[TOTW];      // weights lo, n-major
__device__ __align__(16) __nv_bfloat16 g_xs_h[Nn * FIN]; // x split hi
__device__ __align__(16) __nv_bfloat16 g_xs_l[Nn * FIN]; // x split lo
__device__ __align__(16) __nv_bfloat16 g_hs_h[Nn * Hh];  // h split hi
__device__ __align__(16) __nv_bfloat16 g_hs_l[Nn * Hh];  // h split lo

// ---------------- weight split/convert (fp32 -> bf16 hi/lo, n-major) ---------
__global__ void wconvert_kernel(const float* __restrict__ Win, const float* __restrict__ Wl,
                                const float* __restrict__ Wr, const float* __restrict__ W1)
{
    int i = blockIdx.x * blockDim.x + threadIdx.x;
    if (i < Nn) g_deg[i] = 1;               // self-loop deg init (fused)
    if (i < 64) g_dbin[i] = 0;              // degree-bucket reset (fused)
    if (i >= TOTW) return;
    float v;
    if (i < OFF_WLR) {                       // Win [64,128] -> n-major [128][64]
        int n = i >> 6, k = i & 63;
        v = Win[k * 128 + n];
    } else if (i < OFF_W1) {                 // Wl||Wr per layer -> [256][128]
        int j = i - OFF_WLR;
        int l = j >> 15, r = j & 32767;
        int n = r >> 7, k = r & 127;
        v = (n < 128) ? Wl[l * 16384 + k * 128 + n]
                      : Wr[l * 16384 + k * 128 + (n - 128)];
    } else {                                 // W1 [128,64] -> n-major [64][128]
        int j = i - OFF_W1;
        int n = j >> 7, k = j & 127;
        v = W1[k * 64 + n];
    }
    __nv_bfloat16 hi = __float2bfloat16(v);
    g_bwh[i] = hi;
    g_bwl[i] = __float2bfloat16(v - __bfloat162float(hi));
}

// x split + edge histogram (fused: grid covers Nn*FIN >= Ee)
__global__ void xconvert_kernel(const float* __restrict__ x, const int* __restrict__ dst) {
    int i = blockIdx.x * blockDim.x + threadIdx.x;
    if (i < Nn * FIN) {
        float v = x[i];
        __nv_bfloat16 hi = __float2bfloat16(v);
        g_xs_h[i] = hi;
        g_xs_l[i] = __float2bfloat16(v - __bfloat162float(hi));
    }
    if (i < Ee) atomicAdd(&g_deg[dst[i]], 1);
}

// ---------------- CSR build (+ fused degree bucket sort) ---------------------
__global__ void scan1_kernel() {
    __shared__ int sm[1024];
    __shared__ int sb[64];
    if (threadIdx.x < 64) sb[threadIdx.x] = 0;
    int i = blockIdx.x * 1024 + threadIdx.x;
    int v = (i < Nn) ? g_deg[i] : 0;
    sm[threadIdx.x] = v;
    __syncthreads();
    if (i < Nn) atomicAdd(&sb[min(v - 1, 63)], 1);
    #pragma unroll
    for (int off = 1; off < 1024; off <<= 1) {
        int t = 0;
        if ((int)threadIdx.x >= off) t = sm[threadIdx.x - off];
        __syncthreads();
        sm[threadIdx.x] += t;
        __syncthreads();
    }
    if (i < Nn) g_incl[i] = sm[threadIdx.x];
    if (threadIdx.x == 1023) g_bsums[blockIdx.x] = sm[1023];
    if (threadIdx.x < 64 && sb[threadIdx.x])
        atomicAdd(&g_dbin[threadIdx.x], sb[threadIdx.x]);
}

__global__ void scan3_kernel() {
    __shared__ int base_s;
    if (threadIdx.x == 0) {
        int b = 0;
        for (int j = 0; j < (int)blockIdx.x; ++j) b += g_bsums[j];
        base_s = b;
    }
    if (blockIdx.x == 0 && threadIdx.x == 1) {
        int run = 0;
        for (int j = 0; j < 64; ++j) { int t = g_dbin[j]; g_dcur[j] = run; run += t; }
    }
    __syncthreads();
    int i = blockIdx.x * 1024 + threadIdx.x;
    if (i < Nn) {
        int val = g_incl[i] + base_s;
        g_rowptr[i + 1] = val;
        g_cursor[i + 1] = val;
        if (i == 0) { g_rowptr[0] = 0; g_cursor[0] = 0; }
    }
}

__global__ void scatter_kernel(const int* __restrict__ src, const int* __restrict__ dst) {
    int e = blockIdx.x * blockDim.x + threadIdx.x;
    if (e < EN) {
        int s, d;
        if (e < Ee) { s = src[e]; d = dst[e]; }
        else        { s = d = e - Ee; }
        int p = atomicAdd(&g_cursor[d], 1);
        g_esrc[p] = s;
    }
    if (e < Nn) {
        int b = min(g_deg[e] - 1, 63);
        int p = atomicAdd(&g_dcur[b], 1);
        g_order[p] = e;
    }
}

// ---------------- bf16x3 tensor-core GEMM (32x64 warp tiles, cp.async) -------
__device__ __forceinline__ void mma16816(float* c, const unsigned* a, const unsigned* b) {
    asm volatile(
        "mma.sync.aligned.m16n8k16.row.col.f32.bf16.bf16.f32 "
        "{%0,%1,%2,%3},{%4,%5,%6,%7},{%8,%9},{%0,%1,%2,%3};"
        : "+f"(c[0]), "+f"(c[1]), "+f"(c[2]), "+f"(c[3])
        : "r"(a[0]), "r"(a[1]), "r"(a[2]), "r"(a[3]), "r"(b[0]), "r"(b[1]));
}

__device__ __forceinline__ void ldsm4(unsigned* r, const __nv_bfloat16* p) {
    unsigned addr = (unsigned)__cvta_generic_to_shared(p);
    asm volatile("ldmatrix.sync.aligned.m8n8.x4.shared.b16 {%0,%1,%2,%3},[%4];"
                 : "=r"(r[0]), "=r"(r[1]), "=r"(r[2]), "=r"(r[3]) : "r"(addr));
}

__device__ __forceinline__ void cpa16(uint32_t dst, const void* src, uint32_t srcsz) {
    asm volatile("cp.async.ca.shared.global [%0], [%1], 16, %2;"
                 :: "r"(dst), "l"(src), "r"(srcsz) : "memory");
}
#define CPA_COMMIT() asm volatile("cp.async.commit_group;" ::: "memory")

#define ARR_E   (128 * 40)
#define BUF_E   (4 * ARR_E)
#define SMEM_B  (2 * BUF_E * 2)          // bytes = 81920

extern __shared__ __nv_bfloat16 smbf[];

__global__ void __launch_bounds__(256, 2) gemm3_kernel(
    const __nv_bfloat16* __restrict__ Ah, const __nv_bfloat16* __restrict__ Al, int lda,
    const __nv_bfloat16* __restrict__ Bh, const __nv_bfloat16* __restrict__ Bl,
    const float* __restrict__ bias0, const float* __restrict__ bias1,
    float* __restrict__ C0, float* __restrict__ C1, __half* __restrict__ C0h,
    __nv_bfloat16* __restrict__ Sh, __nv_bfloat16* __restrict__ Sl,
    int M, int K, int Nvalid, int nsplit, int ldc, int relu)
{
    const int tid = threadIdx.x;
    const int lane = tid & 31;
    const int wid = tid >> 5;
    const int warp_m = wid >> 1;
    const int warp_n = wid & 1;
    const int mrow = lane & 7;
    const int mat  = lane >> 3;

    const int row0 = blockIdx.x * 128;
    const int col0 = blockIdx.y * 128;
    const bool wvalid = (col0 + warp_n * 64) < Nvalid;

    float acc[2][8][4];
    #pragma unroll
    for (int a = 0; a < 2; ++a)
        #pragma unroll
        for (int b = 0; b < 8; ++b)
            #pragma unroll
            for (int c = 0; c < 4; ++c) acc[a][b][c] = 0.f;

    const int r  = tid >> 1;     // 0..127
    const int hf = tid & 1;
    const uint32_t smaddr = (uint32_t)__cvta_generic_to_shared(smbf);
    const uint32_t arow_sz = ((row0 + r) < M) ? 16u : 0u;
    const uint32_t brow_sz = ((col0 + r) < Nvalid) ? 16u : 0u;
    const int nk = K >> 5;

    #define STAGE(ck, buf) do {                                                      \
        int kk_ = (ck) * 32;                                                         \
        uint32_t base_ = smaddr + (uint32_t)((buf) * BUF_E) * 2u;                    \
        uint32_t doff_ = (uint32_t)(r * 40 + hf * 16) * 2u;                          \
        const __nv_bfloat16* pah_ = Ah + (size_t)(row0 + r) * lda + kk_ + hf * 16;   \
        const __nv_bfloat16* pal_ = Al + (size_t)(row0 + r) * lda + kk_ + hf * 16;   \
        cpa16(base_ + doff_,                    pah_,     arow_sz);                  \
        cpa16(base_ + doff_ + 16,               pah_ + 8, arow_sz);                  \
        cpa16(base_ + ARR_E * 2 + doff_,        pal_,     arow_sz);                  \
        cpa16(base_ + ARR_E * 2 + doff_ + 16,   pal_ + 8, arow_sz);                  \
        const __nv_bfloat16* pbh_ = Bh + (size_t)(col0 + r) * K + kk_ + hf * 16;     \
        const __nv_bfloat16* pbl_ = Bl + (size_t)(col0 + r) * K + kk_ + hf * 16;     \
        cpa16(base_ + ARR_E * 4 + doff_,        pbh_,     brow_sz);                  \
        cpa16(base_ + ARR_E * 4 + doff_ + 16,   pbh_ + 8, brow_sz);                  \
        cpa16(base_ + ARR_E * 6 + doff_,        pbl_,     brow_sz);                  \
        cpa16(base_ + ARR_E * 6 + doff_ + 16,   pbl_ + 8, brow_sz);                  \
        CPA_COMMIT();                                                                \
    } while (0)

    STAGE(0, 0);

    for (int ci = 0; ci < nk; ++ci) {
        if (ci + 1 < nk) {
            STAGE(ci + 1, (ci + 1) & 1);
            asm volatile("cp.async.wait_group 1;" ::: "memory");
        } else {
            asm volatile("cp.async.wait_group 0;" ::: "memory");
        }
        __syncthreads();

        if (wvalid) {
            const __nv_bfloat16* sAh = smbf + (ci & 1) * BUF_E;
            const __nv_bfloat16* sAl = sAh + ARR_E;
            const __nv_bfloat16* sBh = sAh + 2 * ARR_E;
            const __nv_bfloat16* sBl = sAh + 3 * ARR_E;

            #pragma unroll
            for (int ks = 0; ks < 2; ++ks) {
                const int ck = ks * 16;
                unsigned ah[2][4], al[2][4];
                #pragma unroll
                for (int mt = 0; mt < 2; ++mt) {
                    int ar  = warp_m * 32 + mt * 16 + ((mat & 1) << 3) + mrow;
                    int acl = ck + ((mat >> 1) << 3);
                    ldsm4(ah[mt], sAh + ar * 40 + acl);
                    ldsm4(al[mt], sAl + ar * 40 + acl);
                }
                #pragma unroll
                for (int p = 0; p < 4; ++p) {
                    unsigned bh4[4], bl4[4];
                    int bn  = warp_n * 64 + p * 16 + ((mat >> 1) << 3) + mrow;
                    int bcl = ck + ((mat & 1) << 3);
                    ldsm4(bh4, sBh + bn * 40 + bcl);
                    ldsm4(bl4, sBl + bn * 40 + bcl);
                    #pragma unroll
                    for (int half = 0; half < 2; ++half) {
                        int nt = p * 2 + half;
                        #pragma unroll
                        for (int mt = 0; mt < 2; ++mt) {
                            mma16816(acc[mt][nt], ah[mt], &bh4[half * 2]);
                            mma16816(acc[mt][nt], al[mt], &bh4[half * 2]);
                            mma16816(acc[mt][nt], ah[mt], &bl4[half * 2]);
                        }
                    }
                }
            }
        }
        __syncthreads();
    }

    // ---- epilogue ----
    if (!wvalid) return;
    const float* bp;
    int colbase;
    int useC1 = (col0 >= nsplit);
    if (useC1) { bp = bias1; colbase = col0 - nsplit; }
    else       { bp = bias0; colbase = col0; }

    const int g = lane >> 2, qt = lane & 3;
    #pragma unroll
    for (int mt = 0; mt < 2; ++mt) {
        #pragma unroll
        for (int nt = 0; nt < 8; ++nt) {
            int gcol = col0 + warp_n * 64 + nt * 8 + 2 * qt;
            if (gcol < Nvalid) {
                int oc = colbase + warp_n * 64 + nt * 8 + 2 * qt;
                float b0 = bp[oc], b1 = bp[oc + 1];
                int ra = row0 + warp_m * 32 + mt * 16 + g;
                float v0 = acc[mt][nt][0] + b0, v1 = acc[mt][nt][1] + b1;
                float v2 = acc[mt][nt][2] + b0, v3 = acc[mt][nt][3] + b1;
                if (relu) {
                    v0 = fmaxf(v0, 0.f); v1 = fmaxf(v1, 0.f);
                    v2 = fmaxf(v2, 0.f); v3 = fmaxf(v3, 0.f);
                }
                if (useC1) {
                    if (ra < M)
                        *(float2*)(C1 + (size_t)ra * ldc + oc) = make_float2(v0, v1);
                    if (ra + 8 < M)
                        *(float2*)(C1 + (size_t)(ra + 8) * ldc + oc) = make_float2(v2, v3);
                } else if (C0h) {
                    if (ra < M)
                        *(__half2*)(C0h + (size_t)ra * ldc + oc) = __floats2half2_rn(v0, v1);
                    if (ra + 8 < M)
                        *(__half2*)(C0h + (size_t)(ra + 8) * ldc + oc) = __floats2half2_rn(v2, v3);
                } else {
                    if (ra < M) {
                        *(float2*)(C0 + (size_t)ra * ldc + oc) = make_float2(v0, v1);
                        if (Sh) {
                            __nv_bfloat16 h0 = __float2bfloat16(v0), h1 = __float2bfloat16(v1);
                            *(__nv_bfloat162*)(Sh + (size_t)ra * ldc + oc) = make_bfloat162(h0, h1);
                            *(__nv_bfloat162*)(Sl + (size_t)ra * ldc + oc) =
                                make_bfloat162(__float2bfloat16(v0 - __bfloat162float(h0)),
                                               __float2bfloat16(v1 - __bfloat162float(h1)));
                        }
                    }
                    if (ra + 8 < M) {
                        *(float2*)(C0 + (size_t)(ra + 8) * ldc + oc) = make_float2(v2, v3);
                        if (Sh) {
                            __nv_bfloat16 h2 = __float2bfloat16(v2), h3 = __float2bfloat16(v3);
                            *(__nv_bfloat162*)(Sh + (size_t)(ra + 8) * ldc + oc) = make_bfloat162(h2, h3);
                            *(__nv_bfloat162*)(Sl + (size_t)(ra + 8) * ldc + oc) =
                                make_bfloat162(__float2bfloat16(v2 - __bfloat162float(h2)),
                                               __float2bfloat16(v3 - __bfloat162float(h3)));
                        }
                    }
                }
            }
        }
    }
}

// ---------------- fused GATv2: 2 deg-matched nodes/warp, 16 lanes/node -------
__global__ void gat_kernel(const float* __restrict__ att, const float* __restrict__ bg,
                           const float* __restrict__ lng, const float* __restrict__ lnb,
                           int use_res, int do_relu)
{
    int gwarp = (blockIdx.x * blockDim.x + threadIdx.x) >> 5;
    if (gwarp >= Nn / 2) return;
    int lane = threadIdx.x & 31;
    int grp  = lane >> 4;
    int sl   = lane & 15;
    int node = g_order[gwarp * 2 + grp];    // degree-matched pairing
    int fo   = sl * 8;

    float xr[8], at[8], acc[8];
    *(float4*)&xr[0] = *(const float4*)(g_xr + (size_t)node * Hh + fo);
    *(float4*)&xr[4] = *(const float4*)(g_xr + (size_t)node * Hh + fo + 4);
    *(float4*)&at[0] = *(const float4*)(att + fo);
    *(float4*)&at[4] = *(const float4*)(att + fo + 4);
    #pragma unroll
    for (int k = 0; k < 8; ++k) acc[k] = 0.f;

    int beg = g_rowptr[node], end = g_rowptr[node + 1];
    int deg = end - beg;
    int mdeg = max(deg, __shfl_xor_sync(0xffffffffu, deg, 16));

    float z = 0.f;

    for (int jj = 0; jj < mdeg; jj += 4) {
        float av[4][8];
        float tv[4];
        #pragma unroll
        for (int q = 0; q < 4; ++q) {
            bool valid = (jj + q) < deg;
            int u = g_esrc[valid ? (beg + jj + q) : beg];
            uint4 rw = *(const uint4*)(g_xlh + ((unsigned)u << 7) + fo);
            float2 f;
            f = __half22float2(*(__half2*)&rw.x); av[q][0] = f.x; av[q][1] = f.y;
            f = __half22float2(*(__half2*)&rw.y); av[q][2] = f.x; av[q][3] = f.y;
            f = __half22float2(*(__half2*)&rw.z); av[q][4] = f.x; av[q][5] = f.y;
            f = __half22float2(*(__half2*)&rw.w); av[q][6] = f.x; av[q][7] = f.y;
            float t1 = 0.f, t2 = 0.f;
            #pragma unroll
            for (int k = 0; k < 8; ++k) {
                float e = av[q][k] + xr[k];
                t1 = fmaf(at[k], e, t1);
                t2 = fmaf(at[k], fabsf(e), t2);
            }
            float t = fmaf(0.4f, t2, 0.6f * t1);   // exact leaky identity
            tv[q] = valid ? t : -INFINITY;
        }
        #pragma unroll
        for (int off = 8; off; off >>= 1) {
            #pragma unroll
            for (int q = 0; q < 4; ++q)
                tv[q] += __shfl_xor_sync(0xffffffffu, tv[q], off);
        }
        #pragma unroll
        for (int q = 0; q < 4; ++q) {
            float w = __expf(tv[q]);        // exp(-inf) = 0 for pad slots
            z += w;
            #pragma unroll
            for (int k = 0; k < 8; ++k) acc[k] += w * av[q][k];
        }
    }

    float inv = __fdividef(1.f, z);
    float o[8];
    {
        float4 b0 = *(const float4*)(bg + fo);
        float4 b1 = *(const float4*)(bg + fo + 4);
        o[0] = acc[0] * inv + b0.x; o[1] = acc[1] * inv + b0.y;
        o[2] = acc[2] * inv + b0.z; o[3] = acc[3] * inv + b0.w;
        o[4] = acc[4] * inv + b1.x; o[5] = acc[5] * inv + b1.y;
        o[6] = acc[6] * inv + b1.z; o[7] = acc[7] * inv + b1.w;
    }
    if (use_res) {
        float4 r0 = *(const float4*)(g_h + (size_t)node * Hh + fo);
        float4 r1 = *(const float4*)(g_h + (size_t)node * Hh + fo + 4);
        o[0] += r0.x; o[1] += r0.y; o[2] += r0.z; o[3] += r0.w;
        o[4] += r1.x; o[5] += r1.y; o[6] += r1.z; o[7] += r1.w;
    }

    float s1 = 0.f, s2 = 0.f;
    #pragma unroll
    for (int k = 0; k < 8; ++k) { s1 += o[k]; s2 += o[k] * o[k]; }
    #pragma unroll
    for (int off = 8; off; off >>= 1) {
        s1 += __shfl_xor_sync(0xffffffffu, s1, off);
        s2 += __shfl_xor_sync(0xffffffffu, s2, off);
    }
    float mean = s1 * (1.f / Hh);
    float var  = s2 * (1.f / Hh) - mean * mean;
    float rs = rsqrtf(var + LNEPS);
    {
        float4 g0 = *(const float4*)(lng + fo);
        float4 g1 = *(const float4*)(lng + fo + 4);
        float4 b0 = *(const float4*)(lnb + fo);
        float4 b1 = *(const float4*)(lnb + fo + 4);
        float gv[8] = {g0.x, g0.y, g0.z, g0.w, g1.x, g1.y, g1.z, g1.w};
        float bv[8] = {b0.x, b0.y, b0.z, b0.w, b1.x, b1.y, b1.z, b1.w};
        #pragma unroll
        for (int k = 0; k < 8; ++k) {
            o[k] = (o[k] - mean) * rs * gv[k] + bv[k];
            if (do_relu) o[k] = fmaxf(o[k], 0.f);
        }
    }

    size_t base = (size_t)node * Hh + fo;
    *(float4*)(g_h + base)     = make_float4(o[0], o[1], o[2], o[3]);
    *(float4*)(g_h + base + 4) = make_float4(o[4], o[5], o[6], o[7]);
    #pragma unroll
    for (int k = 0; k < 8; k += 2) {
        __nv_bfloat16 h0 = __float2bfloat16(o[k]), h1 = __float2bfloat16(o[k + 1]);
        *(__nv_bfloat162*)(g_hs_h + base + k) = make_bfloat162(h0, h1);
        *(__nv_bfloat162*)(g_hs_l + base + k) =
            make_bfloat162(__float2bfloat16(o[k] - __bfloat162float(h0)),
                           __float2bfloat16(o[k + 1] - __bfloat162float(h1)));
    }
}

// ---------------- final [N,64] @ [64,2] + b2 ---------------------------------
__global__ void mlp_out_kernel(const float* __restrict__ W2, const float* __restrict__ b2,
                               float* __restrict__ out)
{
    int warp = (blockIdx.x * blockDim.x + threadIdx.x) >> 5;
    if (warp >= Nn) return;
    int lane = threadIdx.x & 31;
    float v0 = g_xl[(size_t)warp * 64 + lane];
    float v1 = g_xl[(size_t)warp * 64 + lane + 32];
    float p0 = v0 * W2[lane * 2 + 0] + v1 * W2[(lane + 32) * 2 + 0];
    float p1 = v0 * W2[lane * 2 + 1] + v1 * W2[(lane + 32) * 2 + 1];
    #pragma unroll
    for (int off = 16; off; off >>= 1) {
        p0 += __shfl_xor_sync(0xffffffffu, p0, off);
        p1 += __shfl_xor_sync(0xffffffffu, p1, off);
    }
    if (lane == 0) {
        out[(size_t)warp * 2 + 0] = p0 + b2[0];
        out[(size_t)warp * 2 + 1] = p1 + b2[1];
    }
}

// -----------------------------------------------------------------------------
extern "C" void kernel_launch(void* const* d_in, const int* in_sizes, int n_in,
                              void* d_out, int out_size)
{
    (void)in_sizes; (void)n_in; (void)out_size;
    const float* x    = (const float*)d_in[0];
    const int*   ei   = (const int*)  d_in[1];
    const float* Win  = (const float*)d_in[2];
    const float* bin_ = (const float*)d_in[3];
    const float* Wl   = (const float*)d_in[4];
    const float* bl   = (const float*)d_in[5];
    const float* Wr   = (const float*)d_in[6];
    const float* br   = (const float*)d_in[7];
    const float* att  = (const float*)d_in[8];
    const float* bg   = (const float*)d_in[9];
    const float* lng  = (const float*)d_in[10];
    const float* lnb  = (const float*)d_in[11];
    const float* W1   = (const float*)d_in[12];
    const float* b1   = (const float*)d_in[13];
    const float* W2   = (const float*)d_in[14];
    const float* b2   = (const float*)d_in[15];
    float* out = (float*)d_out;

    const int* srcp = ei;
    const int* dstp = ei + Ee;

    float *p_h, *p_xl, *p_xr;
    __half* p_xlh;
    __nv_bfloat16 *p_bwh, *p_bwl, *p_xsh, *p_xsl, *p_hsh, *p_hsl;
    cudaGetSymbolAddress((void**)&p_h,   g_h);
    cudaGetSymbolAddress((void**)&p_xl,  g_xl);
    cudaGetSymbolAddress((void**)&p_xr,  g_xr);
    cudaGetSymbolAddress((void**)&p_xlh, g_xlh);
    cudaGetSymbolAddress((void**)&p_bwh, g_bwh);
    cudaGetSymbolAddress((void**)&p_bwl, g_bwl);
    cudaGetSymbolAddress((void**)&p_xsh, g_xs_h);
    cudaGetSymbolAddress((void**)&p_xsl, g_xs_l);
    cudaGetSymbolAddress((void**)&p_hsh, g_hs_h);
    cudaGetSymbolAddress((void**)&p_hsl, g_hs_l);

    const int GX = (Nn + 127) / 128;   // 391
    const int BIG = 1 << 30;
    const int GAT_BLOCKS = (Nn / 2 * 32) / 256;   // 3125

    cudaFuncSetAttribute(gemm3_kernel, cudaFuncAttributeMaxDynamicSharedMemorySize, SMEM_B);

    // side stream + fork/join events (created per call; leaked deliberately —
    // streams/events are not device memory and destroy-during-capture is unsafe)
    cudaStream_t s1;
    cudaEvent_t evFork, evJoin;
    cudaStreamCreateWithFlags(&s1, cudaStreamNonBlocking);
    cudaEventCreateWithFlags(&evFork, cudaEventDisableTiming);
    cudaEventCreateWithFlags(&evJoin, cudaEventDisableTiming);

    // 0: weight convert (+deg init, +dbin reset)   1: x convert (+hist)
    wconvert_kernel<<<(TOTW + 255) / 256, 256>>>(Win, Wl, Wr, W1);
    xconvert_kernel<<<(Nn * FIN + 255) / 256, 256>>>(x, dstp);
    cudaEventRecord(evFork, 0);             // fork point: g_deg complete
    // 2: input projection h = relu(x @ Win + bin), emits split-bf16 h
    gemm3_kernel<<<dim3(GX, 1), 256, SMEM_B>>>(p_xsh, p_xsl, FIN,
                                       p_bwh + OFF_WIN, p_bwl + OFF_WIN,
                                       bin_, bin_, p_h, p_h, nullptr, p_hsh, p_hsl,
                                       Nn, FIN, Hh, BIG, Hh, 1);
    // 3: layer-0 fused Wl||Wr GEMM (ncu-profiled slot); xl -> fp16, xr -> fp32
    gemm3_kernel<<<dim3(GX, 2), 256, SMEM_B>>>(p_hsh, p_hsl, Hh,
                                       p_bwh + OFF_WLR, p_bwl + OFF_WLR,
                                       bl, br, nullptr, p_xr, p_xlh, nullptr, nullptr,
                                       Nn, Hh, 256, Hh, Hh, 0);
    // side branch: CSR build (+fused degree sort), overlaps the two GEMMs above
    cudaStreamWaitEvent(s1, evFork, 0);
    scan1_kernel<<<NB_SCAN, 1024, 0, s1>>>();
    scan3_kernel<<<NB_SCAN, 1024, 0, s1>>>();
    scatter_kernel<<<(EN + 255) / 256, 256, 0, s1>>>(srcp, dstp);
    cudaEventRecord(evJoin, s1);
    cudaStreamWaitEvent(0, evJoin, 0);      // join before attention
    // layer-0 attention
    gat_kernel<<<GAT_BLOCKS, 256>>>(att, bg, lng, lnb, 0, 1);
    // layers 1..2
    for (int i = 1; i < 3; ++i) {
        gemm3_kernel<<<dim3(GX, 2), 256, SMEM_B>>>(p_hsh, p_hsl, Hh,
                                           p_bwh + OFF_WLR + (size_t)i * 256 * 128,
                                           p_bwl + OFF_WLR + (size_t)i * 256 * 128,
                                           bl + (size_t)i * Hh, br + (size_t)i * Hh,
                                           nullptr, p_xr, p_xlh, nullptr, nullptr,
                                           Nn, Hh, 256, Hh, Hh, 0);
        gat_kernel<<<GAT_BLOCKS, 256>>>(att + (size_t)i * Hh, bg + (size_t)i * Hh,
                                        lng + (size_t)i * Hh, lnb + (size_t)i * Hh,
                                        1, (i < 2) ? 1 : 0);
    }
    // output MLP: t1 = relu(h @ W1 + b1) -> g_xl [N,64] (fp32), then @ W2 + b2
    gemm3_kernel<<<dim3(GX, 1), 256, SMEM_B>>>(p_hsh, p_hsl, Hh,
                                       p_bwh + OFF_W1, p_bwl + OFF_W1,
                                       b1, b1, p_xl, p_xl, nullptr, nullptr, nullptr,
                                       Nn, Hh, 64, BIG, 64, 1);
    mlp_out_kernel<<<(Nn * 32 + 255) / 256, 256>>>(W2, b2, out);
}

// round 17
// speedup vs baseline: 1.2653x; 1.0296x over previous
#include <cuda_runtime.h>
#include <cuda_bf16.h>
#include <cuda_fp16.h>
#include <math.h>
#include <stdint.h>

#define Nn   50000
#define Ee   800000
#define EN   (Ee + Nn)
#define Hh   128
#define FIN  64
#define NEGS 0.2f
#define LNEPS 1e-5f
#define NB_SCAN 49   // ceil(50000/1024)

#define OFF_WIN 0
#define OFF_WLR 8192                     // 128*64
#define OFF_W1  (8192 + 3 * 256 * 128)   // 106496
#define TOTW    (OFF_W1 + 64 * 128)      // 114688

// ---------------- scratch (static device globals; no allocation) -------------
__device__ float g_h [Nn * Hh];
__device__ float g_xl[Nn * Hh];          // scratch
__device__ float g_xr[Nn * Hh];
__device__ __align__(16) __half g_xlh[Nn * Hh];   // xl in fp16 for the gather
__device__ int   g_deg[Nn];
__device__ int   g_incl[Nn];
__device__ int   g_rowptr[Nn + 1];
__device__ int   g_cursor[Nn + 1];
__device__ int   g_esrc[EN];
__device__ int   g_bsums[64];
__device__ int   g_dbin[64];             // degree-bucket counts
__device__ int   g_dcur[64];             // degree-bucket cursors
__device__ int   g_order[Nn];            // nodes sorted by degree
__device__ __align__(16) __nv_bfloat16 g_bwh[TOTW];      // weights hi, n-major
__device__ __align__(16) __nv_bfloat16 g_bwl[TOTW];      // weights lo, n-major
__device__ __align__(16) __nv_bfloat16 g_xs_h[Nn * FIN]; // x split hi
__device__ __align__(16) __nv_bfloat16 g_xs_l[Nn * FIN]; // x split lo
__device__ __align__(16) __nv_bfloat16 g_hs_h[Nn * Hh];  // h split hi
__device__ __align__(16) __nv_bfloat16 g_hs_l[Nn * Hh];  // h split lo

// ---------------- weight split/convert (fp32 -> bf16 hi/lo, n-major) ---------
__global__ void wconvert_kernel(const float* __restrict__ Win, const float* __restrict__ Wl,
                                const float* __restrict__ Wr, const float* __restrict__ W1)
{
    int i = blockIdx.x * blockDim.x + threadIdx.x;
    if (i < Nn) g_deg[i] = 1;               // self-loop deg init (fused)
    if (i < 64) g_dbin[i] = 0;              // degree-bucket reset (fused)
    if (i >= TOTW) return;
    float v;
    if (i < OFF_WLR) {                       // Win [64,128] -> n-major [128][64]
        int n = i >> 6, k = i & 63;
        v = Win[k * 128 + n];
    } else if (i < OFF_W1) {                 // Wl||Wr per layer -> [256][128]
        int j = i - OFF_WLR;
        int l = j >> 15, r = j & 32767;
        int n = r >> 7, k = r & 127;
        v = (n < 128) ? Wl[l * 16384 + k * 128 + n]
                      : Wr[l * 16384 + k * 128 + (n - 128)];
    } else {                                 // W1 [128,64] -> n-major [64][128]
        int j = i - OFF_W1;
        int n = j >> 7, k = j & 127;
        v = W1[k * 64 + n];
    }
    __nv_bfloat16 hi = __float2bfloat16(v);
    g_bwh[i] = hi;
    g_bwl[i] = __float2bfloat16(v - __bfloat162float(hi));
}

// x split + edge histogram (fused: grid covers Nn*FIN >= Ee)
__global__ void xconvert_kernel(const float* __restrict__ x, const int* __restrict__ dst) {
    int i = blockIdx.x * blockDim.x + threadIdx.x;
    if (i < Nn * FIN) {
        float v = x[i];
        __nv_bfloat16 hi = __float2bfloat16(v);
        g_xs_h[i] = hi;
        g_xs_l[i] = __float2bfloat16(v - __bfloat162float(hi));
    }
    if (i < Ee) atomicAdd(&g_deg[dst[i]], 1);
}

// ---------------- CSR build (+ fused degree bucket sort) ---------------------
__global__ void scan1_kernel() {
    __shared__ int sm[1024];
    __shared__ int sb[64];
    if (threadIdx.x < 64) sb[threadIdx.x] = 0;
    int i = blockIdx.x * 1024 + threadIdx.x;
    int v = (i < Nn) ? g_deg[i] : 0;
    sm[threadIdx.x] = v;
    __syncthreads();
    if (i < Nn) atomicAdd(&sb[min(v - 1, 63)], 1);
    #pragma unroll
    for (int off = 1; off < 1024; off <<= 1) {
        int t = 0;
        if ((int)threadIdx.x >= off) t = sm[threadIdx.x - off];
        __syncthreads();
        sm[threadIdx.x] += t;
        __syncthreads();
    }
    if (i < Nn) g_incl[i] = sm[threadIdx.x];
    if (threadIdx.x == 1023) g_bsums[blockIdx.x] = sm[1023];
    if (threadIdx.x < 64 && sb[threadIdx.x])
        atomicAdd(&g_dbin[threadIdx.x], sb[threadIdx.x]);
}

__global__ void scan3_kernel() {
    __shared__ int base_s;
    if (threadIdx.x == 0) {
        int b = 0;
        for (int j = 0; j < (int)blockIdx.x; ++j) b += g_bsums[j];
        base_s = b;
    }
    if (blockIdx.x == 0 && threadIdx.x == 1) {
        int run = 0;
        for (int j = 0; j < 64; ++j) { int t = g_dbin[j]; g_dcur[j] = run; run += t; }
    }
    __syncthreads();
    int i = blockIdx.x * 1024 + threadIdx.x;
    if (i < Nn) {
        int val = g_incl[i] + base_s;
        g_rowptr[i + 1] = val;
        g_cursor[i + 1] = val;
        if (i == 0) { g_rowptr[0] = 0; g_cursor[0] = 0; }
    }
}

__global__ void scatter_kernel(const int* __restrict__ src, const int* __restrict__ dst) {
    int e = blockIdx.x * blockDim.x + threadIdx.x;
    if (e < EN) {
        int s, d;
        if (e < Ee) { s = src[e]; d = dst[e]; }
        else        { s = d = e - Ee; }
        int p = atomicAdd(&g_cursor[d], 1);
        g_esrc[p] = s;
    }
    if (e < Nn) {
        int b = min(g_deg[e] - 1, 63);
        int p = atomicAdd(&g_dcur[b], 1);
        g_order[p] = e;
    }
}

// ---------------- bf16x3 tensor-core GEMM (32x64 warp tiles, cp.async) -------
// Full 3-term product everywhere (AhBh + AlBh + AhBl) — term dropping proven
// numerically unsafe (R16). Optional fused MLP head: when outp != null the
// epilogue computes out = relu(C) @ W2p + b2p in-warp instead of storing C.
__device__ __forceinline__ void mma16816(float* c, const unsigned* a, const unsigned* b) {
    asm volatile(
        "mma.sync.aligned.m16n8k16.row.col.f32.bf16.bf16.f32 "
        "{%0,%1,%2,%3},{%4,%5,%6,%7},{%8,%9},{%0,%1,%2,%3};"
        : "+f"(c[0]), "+f"(c[1]), "+f"(c[2]), "+f"(c[3])
        : "r"(a[0]), "r"(a[1]), "r"(a[2]), "r"(a[3]), "r"(b[0]), "r"(b[1]));
}

__device__ __forceinline__ void ldsm4(unsigned* r, const __nv_bfloat16* p) {
    unsigned addr = (unsigned)__cvta_generic_to_shared(p);
    asm volatile("ldmatrix.sync.aligned.m8n8.x4.shared.b16 {%0,%1,%2,%3},[%4];"
                 : "=r"(r[0]), "=r"(r[1]), "=r"(r[2]), "=r"(r[3]) : "r"(addr));
}

__device__ __forceinline__ void cpa16(uint32_t dst, const void* src, uint32_t srcsz) {
    asm volatile("cp.async.ca.shared.global [%0], [%1], 16, %2;"
                 :: "r"(dst), "l"(src), "r"(srcsz) : "memory");
}
#define CPA_COMMIT() asm volatile("cp.async.commit_group;" ::: "memory")

#define ARR_E   (128 * 40)
#define BUF_E   (4 * ARR_E)
#define SMEM_B  (2 * BUF_E * 2)          // bytes = 81920

extern __shared__ __nv_bfloat16 smbf[];

__global__ void __launch_bounds__(256, 2) gemm3_kernel(
    const __nv_bfloat16* __restrict__ Ah, const __nv_bfloat16* __restrict__ Al, int lda,
    const __nv_bfloat16* __restrict__ Bh, const __nv_bfloat16* __restrict__ Bl,
    const float* __restrict__ bias0, const float* __restrict__ bias1,
    float* __restrict__ C0, float* __restrict__ C1, __half* __restrict__ C0h,
    __nv_bfloat16* __restrict__ Sh, __nv_bfloat16* __restrict__ Sl,
    const float* __restrict__ W2p, const float* __restrict__ b2p, float* __restrict__ outp,
    int M, int K, int Nvalid, int nsplit, int ldc, int relu)
{
    const int tid = threadIdx.x;
    const int lane = tid & 31;
    const int wid = tid >> 5;
    const int warp_m = wid >> 1;
    const int warp_n = wid & 1;
    const int mrow = lane & 7;
    const int mat  = lane >> 3;

    const int row0 = blockIdx.x * 128;
    const int col0 = blockIdx.y * 128;
    const bool wvalid = (col0 + warp_n * 64) < Nvalid;

    float acc[2][8][4];
    #pragma unroll
    for (int a = 0; a < 2; ++a)
        #pragma unroll
        for (int b = 0; b < 8; ++b)
            #pragma unroll
            for (int c = 0; c < 4; ++c) acc[a][b][c] = 0.f;

    const int r  = tid >> 1;     // 0..127
    const int hf = tid & 1;
    const uint32_t smaddr = (uint32_t)__cvta_generic_to_shared(smbf);
    const uint32_t arow_sz = ((row0 + r) < M) ? 16u : 0u;
    const uint32_t brow_sz = ((col0 + r) < Nvalid) ? 16u : 0u;
    const int nk = K >> 5;

    #define STAGE(ck, buf) do {                                                      \
        int kk_ = (ck) * 32;                                                         \
        uint32_t base_ = smaddr + (uint32_t)((buf) * BUF_E) * 2u;                    \
        uint32_t doff_ = (uint32_t)(r * 40 + hf * 16) * 2u;                          \
        const __nv_bfloat16* pah_ = Ah + (size_t)(row0 + r) * lda + kk_ + hf * 16;   \
        const __nv_bfloat16* pal_ = Al + (size_t)(row0 + r) * lda + kk_ + hf * 16;   \
        cpa16(base_ + doff_,                    pah_,     arow_sz);                  \
        cpa16(base_ + doff_ + 16,               pah_ + 8, arow_sz);                  \
        cpa16(base_ + ARR_E * 2 + doff_,        pal_,     arow_sz);                  \
        cpa16(base_ + ARR_E * 2 + doff_ + 16,   pal_ + 8, arow_sz);                  \
        const __nv_bfloat16* pbh_ = Bh + (size_t)(col0 + r) * K + kk_ + hf * 16;     \
        const __nv_bfloat16* pbl_ = Bl + (size_t)(col0 + r) * K + kk_ + hf * 16;     \
        cpa16(base_ + ARR_E * 4 + doff_,        pbh_,     brow_sz);                  \
        cpa16(base_ + ARR_E * 4 + doff_ + 16,   pbh_ + 8, brow_sz);                  \
        cpa16(base_ + ARR_E * 6 + doff_,        pbl_,     brow_sz);                  \
        cpa16(base_ + ARR_E * 6 + doff_ + 16,   pbl_ + 8, brow_sz);                  \
        CPA_COMMIT();                                                                \
    } while (0)

    STAGE(0, 0);

    for (int ci = 0; ci < nk; ++ci) {
        if (ci + 1 < nk) {
            STAGE(ci + 1, (ci + 1) & 1);
            asm volatile("cp.async.wait_group 1;" ::: "memory");
        } else {
            asm volatile("cp.async.wait_group 0;" ::: "memory");
        }
        __syncthreads();

        if (wvalid) {
            const __nv_bfloat16* sAh = smbf + (ci & 1) * BUF_E;
            const __nv_bfloat16* sAl = sAh + ARR_E;
            const __nv_bfloat16* sBh = sAh + 2 * ARR_E;
            const __nv_bfloat16* sBl = sAh + 3 * ARR_E;

            #pragma unroll
            for (int ks = 0; ks < 2; ++ks) {
                const int ck = ks * 16;
                unsigned ah[2][4], al[2][4];
                #pragma unroll
                for (int mt = 0; mt < 2; ++mt) {
                    int ar  = warp_m * 32 + mt * 16 + ((mat & 1) << 3) + mrow;
                    int acl = ck + ((mat >> 1) << 3);
                    ldsm4(ah[mt], sAh + ar * 40 + acl);
                    ldsm4(al[mt], sAl + ar * 40 + acl);
                }
                #pragma unroll
                for (int p = 0; p < 4; ++p) {
                    unsigned bh4[4], bl4[4];
                    int bn  = warp_n * 64 + p * 16 + ((mat >> 1) << 3) + mrow;
                    int bcl = ck + ((mat & 1) << 3);
                    ldsm4(bh4, sBh + bn * 40 + bcl);
                    ldsm4(bl4, sBl + bn * 40 + bcl);
                    #pragma unroll
                    for (int half = 0; half < 2; ++half) {
                        int nt = p * 2 + half;
                        #pragma unroll
                        for (int mt = 0; mt < 2; ++mt) {
                            mma16816(acc[mt][nt], ah[mt], &bh4[half * 2]);
                            mma16816(acc[mt][nt], al[mt], &bh4[half * 2]);
                            mma16816(acc[mt][nt], ah[mt], &bl4[half * 2]);
                        }
                    }
                }
            }
        }
        __syncthreads();
    }

    // ---- epilogue ----
    if (!wvalid) return;
    const float* bp;
    int colbase;
    int useC1 = (col0 >= nsplit);
    if (useC1) { bp = bias1; colbase = col0 - nsplit; }
    else       { bp = bias0; colbase = col0; }

    const int g = lane >> 2, qt = lane & 3;

    if (outp) {
        // fused MLP head: out[row] = relu(C[row]) @ W2p + b2p  (Nvalid == 64,
        // so each valid warp holds complete 64-col rows; quad shfl completes dots)
        float pr[2][2][2];   // [mt][rowhalf][class]
        #pragma unroll
        for (int a = 0; a < 2; ++a)
            #pragma unroll
            for (int b = 0; b < 2; ++b) { pr[a][b][0] = 0.f; pr[a][b][1] = 0.f; }
        #pragma unroll
        for (int mt = 0; mt < 2; ++mt) {
            #pragma unroll
            for (int nt = 0; nt < 8; ++nt) {
                int oc = nt * 8 + 2 * qt;
                float b0 = bp[oc], b1 = bp[oc + 1];
                float v0 = fmaxf(acc[mt][nt][0] + b0, 0.f);
                float v1 = fmaxf(acc[mt][nt][1] + b1, 0.f);
                float v2 = fmaxf(acc[mt][nt][2] + b0, 0.f);
                float v3 = fmaxf(acc[mt][nt][3] + b1, 0.f);
                float w00 = W2p[oc * 2],       w01 = W2p[oc * 2 + 1];
                float w10 = W2p[(oc + 1) * 2], w11 = W2p[(oc + 1) * 2 + 1];
                pr[mt][0][0] += v0 * w00 + v1 * w10;
                pr[mt][0][1] += v0 * w01 + v1 * w11;
                pr[mt][1][0] += v2 * w00 + v3 * w10;
                pr[mt][1][1] += v2 * w01 + v3 * w11;
            }
        }
        #pragma unroll
        for (int a = 0; a < 2; ++a)
            #pragma unroll
            for (int b = 0; b < 2; ++b)
                #pragma unroll
                for (int c = 0; c < 2; ++c) {
                    pr[a][b][c] += __shfl_xor_sync(0xffffffffu, pr[a][b][c], 1);
                    pr[a][b][c] += __shfl_xor_sync(0xffffffffu, pr[a][b][c], 2);
                }
        if (qt == 0) {
            float o0 = b2p[0], o1 = b2p[1];
            #pragma unroll
            for (int mt = 0; mt < 2; ++mt) {
                #pragma unroll
                for (int rh = 0; rh < 2; ++rh) {
                    int ra = row0 + warp_m * 32 + mt * 16 + rh * 8 + g;
                    if (ra < M) {
                        outp[(size_t)ra * 2 + 0] = pr[mt][rh][0] + o0;
                        outp[(size_t)ra * 2 + 1] = pr[mt][rh][1] + o1;
                    }
                }
            }
        }
        return;
    }

    #pragma unroll
    for (int mt = 0; mt < 2; ++mt) {
        #pragma unroll
        for (int nt = 0; nt < 8; ++nt) {
            int gcol = col0 + warp_n * 64 + nt * 8 + 2 * qt;
            if (gcol < Nvalid) {
                int oc = colbase + warp_n * 64 + nt * 8 + 2 * qt;
                float b0 = bp[oc], b1 = bp[oc + 1];
                int ra = row0 + warp_m * 32 + mt * 16 + g;
                float v0 = acc[mt][nt][0] + b0, v1 = acc[mt][nt][1] + b1;
                float v2 = acc[mt][nt][2] + b0, v3 = acc[mt][nt][3] + b1;
                if (relu) {
                    v0 = fmaxf(v0, 0.f); v1 = fmaxf(v1, 0.f);
                    v2 = fmaxf(v2, 0.f); v3 = fmaxf(v3, 0.f);
                }
                if (useC1) {
                    if (ra < M)
                        *(float2*)(C1 + (size_t)ra * ldc + oc) = make_float2(v0, v1);
                    if (ra + 8 < M)
                        *(float2*)(C1 + (size_t)(ra + 8) * ldc + oc) = make_float2(v2, v3);
                } else if (C0h) {
                    if (ra < M)
                        *(__half2*)(C0h + (size_t)ra * ldc + oc) = __floats2half2_rn(v0, v1);
                    if (ra + 8 < M)
                        *(__half2*)(C0h + (size_t)(ra + 8) * ldc + oc) = __floats2half2_rn(v2, v3);
                } else {
                    if (ra < M) {
                        *(float2*)(C0 + (size_t)ra * ldc + oc) = make_float2(v0, v1);
                        if (Sh) {
                            __nv_bfloat16 h0 = __float2bfloat16(v0), h1 = __float2bfloat16(v1);
                            *(__nv_bfloat162*)(Sh + (size_t)ra * ldc + oc) = make_bfloat162(h0, h1);
                            *(__nv_bfloat162*)(Sl + (size_t)ra * ldc + oc) =
                                make_bfloat162(__float2bfloat16(v0 - __bfloat162float(h0)),
                                               __float2bfloat16(v1 - __bfloat162float(h1)));
                        }
                    }
                    if (ra + 8 < M) {
                        *(float2*)(C0 + (size_t)(ra + 8) * ldc + oc) = make_float2(v2, v3);
                        if (Sh) {
                            __nv_bfloat16 h2 = __float2bfloat16(v2), h3 = __float2bfloat16(v3);
                            *(__nv_bfloat162*)(Sh + (size_t)(ra + 8) * ldc + oc) = make_bfloat162(h2, h3);
                            *(__nv_bfloat162*)(Sl + (size_t)(ra + 8) * ldc + oc) =
                                make_bfloat162(__float2bfloat16(v2 - __bfloat162float(h2)),
                                               __float2bfloat16(v3 - __bfloat162float(h3)));
                        }
                    }
                }
            }
        }
    }
}

// ---------------- fused GATv2: 2 deg-matched nodes/warp, 16 lanes/node -------
__global__ void gat_kernel(const float* __restrict__ att, const float* __restrict__ bg,
                           const float* __restrict__ lng, const float* __restrict__ lnb,
                           int use_res, int do_relu)
{
    int gwarp = (blockIdx.x * blockDim.x + threadIdx.x) >> 5;
    if (gwarp >= Nn / 2) return;
    int lane = threadIdx.x & 31;
    int grp  = lane >> 4;
    int sl   = lane & 15;
    int node = g_order[gwarp * 2 + grp];    // degree-matched pairing
    int fo   = sl * 8;

    float xr[8], at[8], acc[8];
    *(float4*)&xr[0] = *(const float4*)(g_xr + (size_t)node * Hh + fo);
    *(float4*)&xr[4] = *(const float4*)(g_xr + (size_t)node * Hh + fo + 4);
    *(float4*)&at[0] = *(const float4*)(att + fo);
    *(float4*)&at[4] = *(const float4*)(att + fo + 4);
    #pragma unroll
    for (int k = 0; k < 8; ++k) acc[k] = 0.f;

    int beg = g_rowptr[node], end = g_rowptr[node + 1];
    int deg = end - beg;
    int mdeg = max(deg, __shfl_xor_sync(0xffffffffu, deg, 16));

    float z = 0.f;

    for (int jj = 0; jj < mdeg; jj += 4) {
        float av[4][8];
        float tv[4];
        #pragma unroll
        for (int q = 0; q < 4; ++q) {
            bool valid = (jj + q) < deg;
            int u = g_esrc[valid ? (beg + jj + q) : beg];
            uint4 rw = *(const uint4*)(g_xlh + ((unsigned)u << 7) + fo);
            float2 f;
            f = __half22float2(*(__half2*)&rw.x); av[q][0] = f.x; av[q][1] = f.y;
            f = __half22float2(*(__half2*)&rw.y); av[q][2] = f.x; av[q][3] = f.y;
            f = __half22float2(*(__half2*)&rw.z); av[q][4] = f.x; av[q][5] = f.y;
            f = __half22float2(*(__half2*)&rw.w); av[q][6] = f.x; av[q][7] = f.y;
            float t1 = 0.f, t2 = 0.f;
            #pragma unroll
            for (int k = 0; k < 8; ++k) {
                float e = av[q][k] + xr[k];
                t1 = fmaf(at[k], e, t1);
                t2 = fmaf(at[k], fabsf(e), t2);
            }
            float t = fmaf(0.4f, t2, 0.6f * t1);   // exact leaky identity
            tv[q] = valid ? t : -INFINITY;
        }
        #pragma unroll
        for (int off = 8; off; off >>= 1) {
            #pragma unroll
            for (int q = 0; q < 4; ++q)
                tv[q] += __shfl_xor_sync(0xffffffffu, tv[q], off);
        }
        #pragma unroll
        for (int q = 0; q < 4; ++q) {
            float w = __expf(tv[q]);        // exp(-inf) = 0 for pad slots
            z += w;
            #pragma unroll
            for (int k = 0; k < 8; ++k) acc[k] += w * av[q][k];
        }
    }

    float inv = __fdividef(1.f, z);
    float o[8];
    {
        float4 b0 = *(const float4*)(bg + fo);
        float4 b1 = *(const float4*)(bg + fo + 4);
        o[0] = acc[0] * inv + b0.x; o[1] = acc[1] * inv + b0.y;
        o[2] = acc[2] * inv + b0.z; o[3] = acc[3] * inv + b0.w;
        o[4] = acc[4] * inv + b1.x; o[5] = acc[5] * inv + b1.y;
        o[6] = acc[6] * inv + b1.z; o[7] = acc[7] * inv + b1.w;
    }
    if (use_res) {
        float4 r0 = *(const float4*)(g_h + (size_t)node * Hh + fo);
        float4 r1 = *(const float4*)(g_h + (size_t)node * Hh + fo + 4);
        o[0] += r0.x; o[1] += r0.y; o[2] += r0.z; o[3] += r0.w;
        o[4] += r1.x; o[5] += r1.y; o[6] += r1.z; o[7] += r1.w;
    }

    float s1 = 0.f, s2 = 0.f;
    #pragma unroll
    for (int k = 0; k < 8; ++k) { s1 += o[k]; s2 += o[k] * o[k]; }
    #pragma unroll
    for (int off = 8; off; off >>= 1) {
        s1 += __shfl_xor_sync(0xffffffffu, s1, off);
        s2 += __shfl_xor_sync(0xffffffffu, s2, off);
    }
    float mean = s1 * (1.f / Hh);
    float var  = s2 * (1.f / Hh) - mean * mean;
    float rs = rsqrtf(var + LNEPS);
    {
        float4 g0 = *(const float4*)(lng + fo);
        float4 g1 = *(const float4*)(lng + fo + 4);
        float4 b0 = *(const float4*)(lnb + fo);
        float4 b1 = *(const float4*)(lnb + fo + 4);
        float gv[8] = {g0.x, g0.y, g0.z, g0.w, g1.x, g1.y, g1.z, g1.w};
        float bv[8] = {b0.x, b0.y, b0.z, b0.w, b1.x, b1.y, b1.z, b1.w};
        #pragma unroll
        for (int k = 0; k < 8; ++k) {
            o[k] = (o[k] - mean) * rs * gv[k] + bv[k];
            if (do_relu) o[k] = fmaxf(o[k], 0.f);
        }
    }

    size_t base = (size_t)node * Hh + fo;
    *(float4*)(g_h + base)     = make_float4(o[0], o[1], o[2], o[3]);
    *(float4*)(g_h + base + 4) = make_float4(o[4], o[5], o[6], o[7]);
    #pragma unroll
    for (int k = 0; k < 8; k += 2) {
        __nv_bfloat16 h0 = __float2bfloat16(o[k]), h1 = __float2bfloat16(o[k + 1]);
        *(__nv_bfloat162*)(g_hs_h + base + k) = make_bfloat162(h0, h1);
        *(__nv_bfloat162*)(g_hs_l + base + k) =
            make_bfloat162(__float2bfloat16(o[k] - __bfloat162float(h0)),
                           __float2bfloat16(o[k + 1] - __bfloat162float(h1)));
    }
}

// -----------------------------------------------------------------------------
extern "C" void kernel_launch(void* const* d_in, const int* in_sizes, int n_in,
                              void* d_out, int out_size)
{
    (void)in_sizes; (void)n_in; (void)out_size;
    const float* x    = (const float*)d_in[0];
    const int*   ei   = (const int*)  d_in[1];
    const float* Win  = (const float*)d_in[2];
    const float* bin_ = (const float*)d_in[3];
    const float* Wl   = (const float*)d_in[4];
    const float* bl   = (const float*)d_in[5];
    const float* Wr   = (const float*)d_in[6];
    const float* br   = (const float*)d_in[7];
    const float* att  = (const float*)d_in[8];
    const float* bg   = (const float*)d_in[9];
    const float* lng  = (const float*)d_in[10];
    const float* lnb  = (const float*)d_in[11];
    const float* W1   = (const float*)d_in[12];
    const float* b1   = (const float*)d_in[13];
    const float* W2   = (const float*)d_in[14];
    const float* b2   = (const float*)d_in[15];
    float* out = (float*)d_out;

    const int* srcp = ei;
    const int* dstp = ei + Ee;

    float *p_h, *p_xl, *p_xr;
    __half* p_xlh;
    __nv_bfloat16 *p_bwh, *p_bwl, *p_xsh, *p_xsl, *p_hsh, *p_hsl;
    cudaGetSymbolAddress((void**)&p_h,   g_h);
    cudaGetSymbolAddress((void**)&p_xl,  g_xl);
    cudaGetSymbolAddress((void**)&p_xr,  g_xr);
    cudaGetSymbolAddress((void**)&p_xlh, g_xlh);
    cudaGetSymbolAddress((void**)&p_bwh, g_bwh);
    cudaGetSymbolAddress((void**)&p_bwl, g_bwl);
    cudaGetSymbolAddress((void**)&p_xsh, g_xs_h);
    cudaGetSymbolAddress((void**)&p_xsl, g_xs_l);
    cudaGetSymbolAddress((void**)&p_hsh, g_hs_h);
    cudaGetSymbolAddress((void**)&p_hsl, g_hs_l);

    const int GX = (Nn + 127) / 128;   // 391
    const int BIG = 1 << 30;
    const int GAT_BLOCKS = (Nn / 2 * 32) / 256;   // 3125

    cudaFuncSetAttribute(gemm3_kernel, cudaFuncAttributeMaxDynamicSharedMemorySize, SMEM_B);

    // side stream + fork/join events (created per call; not device memory)
    cudaStream_t s1;
    cudaEvent_t evFork, evJoin;
    cudaStreamCreateWithFlags(&s1, cudaStreamNonBlocking);
    cudaEventCreateWithFlags(&evFork, cudaEventDisableTiming);
    cudaEventCreateWithFlags(&evJoin, cudaEventDisableTiming);

    // 0: weight convert (+deg init, +dbin reset)   1: x convert (+hist)
    wconvert_kernel<<<(TOTW + 255) / 256, 256>>>(Win, Wl, Wr, W1);
    xconvert_kernel<<<(Nn * FIN + 255) / 256, 256>>>(x, dstp);
    cudaEventRecord(evFork, 0);             // fork point: g_deg complete
    // 2: input projection h = relu(x @ Win + bin), emits split-bf16 h
    gemm3_kernel<<<dim3(GX, 1), 256, SMEM_B>>>(p_xsh, p_xsl, FIN,
                                       p_bwh + OFF_WIN, p_bwl + OFF_WIN,
                                       bin_, bin_, p_h, p_h, nullptr, p_hsh, p_hsl,
                                       nullptr, nullptr, nullptr,
                                       Nn, FIN, Hh, BIG, Hh, 1);
    // 3: layer-0 fused Wl||Wr GEMM (ncu-profiled slot); xl -> fp16, xr -> fp32
    gemm3_kernel<<<dim3(GX, 2), 256, SMEM_B>>>(p_hsh, p_hsl, Hh,
                                       p_bwh + OFF_WLR, p_bwl + OFF_WLR,
                                       bl, br, nullptr, p_xr, p_xlh, nullptr, nullptr,
                                       nullptr, nullptr, nullptr,
                                       Nn, Hh, 256, Hh, Hh, 0);
    // side branch: CSR build (+fused degree sort), overlaps the two GEMMs above
    cudaStreamWaitEvent(s1, evFork, 0);
    scan1_kernel<<<NB_SCAN, 1024, 0, s1>>>();
    scan3_kernel<<<NB_SCAN, 1024, 0, s1>>>();
    scatter_kernel<<<(EN + 255) / 256, 256, 0, s1>>>(srcp, dstp);
    cudaEventRecord(evJoin, s1);
    cudaStreamWaitEvent(0, evJoin, 0);      // join before attention
    // layer-0 attention
    gat_kernel<<<GAT_BLOCKS, 256>>>(att, bg, lng, lnb, 0, 1);
    // layers 1..2
    for (int i = 1; i < 3; ++i) {
        gemm3_kernel<<<dim3(GX, 2), 256, SMEM_B>>>(p_hsh, p_hsl, Hh,
                                           p_bwh + OFF_WLR + (size_t)i * 256 * 128,
                                           p_bwl + OFF_WLR + (size_t)i * 256 * 128,
                                           bl + (size_t)i * Hh, br + (size_t)i * Hh,
                                           nullptr, p_xr, p_xlh, nullptr, nullptr,
                                           nullptr, nullptr, nullptr,
                                           Nn, Hh, 256, Hh, Hh, 0);
        gat_kernel<<<GAT_BLOCKS, 256>>>(att + (size_t)i * Hh, bg + (size_t)i * Hh,
                                        lng + (size_t)i * Hh, lnb + (size_t)i * Hh,
                                        1, (i < 2) ? 1 : 0);
    }
    // output MLP fused into W1 GEMM epilogue: out = relu(h @ W1 + b1) @ W2 + b2
    gemm3_kernel<<<dim3(GX, 1), 256, SMEM_B>>>(p_hsh, p_hsl, Hh,
                                       p_bwh + OFF_W1, p_bwl + OFF_W1,
                                       b1, b1, p_xl, p_xl, nullptr, nullptr, nullptr,
                                       W2, b2, out,
                                       Nn, Hh, 64, BIG, 64, 1);
}